// round 1
// baseline (speedup 1.0000x reference)
#include <cuda_runtime.h>
#include <cuda_bf16.h>
#include <mma.h>

using namespace nvcuda;

// ---------------- problem constants ----------------
#define BATCH   8
#define HW      112
#define DIM     192
#define HEADS   6
#define HD      32
#define INNER   192
#define MLPD    768
#define WS      7
#define WS2     49
#define NWIN    16          // windows per side
#define TOKENS  (BATCH*HW*HW)        // 100352
#define TOK_IMG (HW*HW)              // 12544

// ---------------- scratch (device globals; no allocs) ----------------
__device__ __nv_bfloat16 g_y   [(size_t)TOKENS*DIM];     // LN1 out (shifted)
__device__ __nv_bfloat16 g_qkv [(size_t)TOKENS*576];     // qkv bf16
__device__ __nv_bfloat16 g_attn[(size_t)TOKENS*INNER];   // attention out (shifted)
__device__ float         g_x2  [(size_t)TOKENS*DIM];     // x + attn branch (unshifted)
__device__ __nv_bfloat16 g_h   [(size_t)TOKENS*DIM];     // LN2 out
__device__ __nv_bfloat16 g_mlp [(size_t)TOKENS*MLPD];    // gelu(mlp1)
__device__ __nv_bfloat16 g_wqkv[DIM*576];
__device__ __nv_bfloat16 g_wout[INNER*DIM];
__device__ __nv_bfloat16 g_w1  [DIM*MLPD];
__device__ __nv_bfloat16 g_w2  [MLPD*DIM];
__device__ float         g_bias[WS2*WS2];                // rel-pos bias table

// ---------------- small utility kernels ----------------
__global__ void f2bf_kernel(const float* __restrict__ in, __nv_bfloat16* __restrict__ out, int n) {
    int i = blockIdx.x * blockDim.x + threadIdx.x;
    if (i < n) out[i] = __float2bfloat16(in[i]);
}

__global__ void relbias_kernel(const float* __restrict__ pos, float* __restrict__ bias) {
    for (int e = threadIdx.x; e < WS2*WS2; e += blockDim.x) {
        int i = e / WS2, j = e % WS2;
        int ri = i / WS, ci = i % WS, rj = j / WS, cj = j % WS;
        bias[e] = pos[(ri - rj + WS - 1) * (2*WS - 1) + (ci - cj + WS - 1)];
    }
}

// LayerNorm; optionally reads input with +3 cyclic shift (fuses jnp.roll(-3,-3))
__global__ void __launch_bounds__(256) ln_kernel(
    const float* __restrict__ in, const float* __restrict__ gam,
    const float* __restrict__ bet, __nv_bfloat16* __restrict__ out, int shift)
{
    int warp = (blockIdx.x * blockDim.x + threadIdx.x) >> 5;
    int lane = threadIdx.x & 31;
    if (warp >= TOKENS) return;
    int t = warp;
    size_t src;
    if (shift) {
        int b = t / TOK_IMG;
        int r = (t / HW) % HW;
        int c = t % HW;
        src = (size_t)(b * TOK_IMG + ((r + 3) % HW) * HW + ((c + 3) % HW)) * DIM;
    } else {
        src = (size_t)t * DIM;
    }
    float v[6];
    float s = 0.f, sq = 0.f;
#pragma unroll
    for (int k = 0; k < 6; k++) {
        v[k] = in[src + lane + 32*k];
        s += v[k]; sq += v[k]*v[k];
    }
#pragma unroll
    for (int o = 16; o > 0; o >>= 1) {
        s  += __shfl_xor_sync(0xffffffffu, s,  o);
        sq += __shfl_xor_sync(0xffffffffu, sq, o);
    }
    float mean = s * (1.f/DIM);
    float var  = sq * (1.f/DIM) - mean*mean;
    float rstd = rsqrtf(var + 1e-5f);
    size_t dst = (size_t)t * DIM;
#pragma unroll
    for (int k = 0; k < 6; k++) {
        int c = lane + 32*k;
        out[dst + c] = __float2bfloat16((v[k] - mean) * rstd * gam[c] + bet[c]);
    }
}

// ---------------- GEMM: C = A[M,K]@B[K,N] (bf16 in, fp32 acc) ----------------
enum { EPI_QKV = 0, EPI_PROJ = 1, EPI_MLP1 = 2, EPI_MLP2 = 3 };

// tiles: 128(M) x 64(N) x 32(K); 8 warps, each 32x32 (2x2 wmma 16x16x16 frags)
template<int EPI>
__global__ void __launch_bounds__(256) gemm_bf16(
    const __nv_bfloat16* __restrict__ A, const __nv_bfloat16* __restrict__ B,
    int K, int N,
    const float* __restrict__ bias, const float* __restrict__ resid,
    float* __restrict__ outF, __nv_bfloat16* __restrict__ outH)
{
    __shared__ __align__(16) unsigned char smem[34816];
    __nv_bfloat16 (*As)[40] = reinterpret_cast<__nv_bfloat16(*)[40]>(smem);            // 128x(32+8)
    __nv_bfloat16 (*Bs)[72] = reinterpret_cast<__nv_bfloat16(*)[72]>(smem + 10240);    // 32x(64+8)
    float         (*Cs)[68] = reinterpret_cast<float(*)[68]>(smem);                    // union: 128x(64+4)

    int tid  = threadIdx.x;
    int warp = tid >> 5;
    int wm   = warp & 3;    // 0..3 -> 32-row strip
    int wn   = warp >> 2;   // 0..1 -> 32-col strip
    int row0 = blockIdx.y * 128;
    int col0 = blockIdx.x * 64;

    wmma::fragment<wmma::accumulator,16,16,16,float> acc[2][2];
#pragma unroll
    for (int i = 0; i < 2; i++)
#pragma unroll
        for (int j = 0; j < 2; j++) wmma::fill_fragment(acc[i][j], 0.f);

    for (int kb = 0; kb < K; kb += 32) {
#pragma unroll
        for (int l = 0; l < 2; l++) {
            int v  = tid + l*256;
            int r  = v >> 2;
            int c8 = (v & 3) * 8;
            *reinterpret_cast<uint4*>(&As[r][c8]) =
                *reinterpret_cast<const uint4*>(A + (size_t)(row0 + r)*K + kb + c8);
        }
        {
            int r  = tid >> 3;
            int c8 = (tid & 7) * 8;
            *reinterpret_cast<uint4*>(&Bs[r][c8]) =
                *reinterpret_cast<const uint4*>(B + (size_t)(kb + r)*N + col0 + c8);
        }
        __syncthreads();
#pragma unroll
        for (int kk = 0; kk < 32; kk += 16) {
            wmma::fragment<wmma::matrix_a,16,16,16,__nv_bfloat16,wmma::row_major> af[2];
            wmma::fragment<wmma::matrix_b,16,16,16,__nv_bfloat16,wmma::row_major> bf[2];
            wmma::load_matrix_sync(af[0], &As[wm*32     ][kk], 40);
            wmma::load_matrix_sync(af[1], &As[wm*32 + 16][kk], 40);
            wmma::load_matrix_sync(bf[0], &Bs[kk][wn*32     ], 72);
            wmma::load_matrix_sync(bf[1], &Bs[kk][wn*32 + 16], 72);
#pragma unroll
            for (int i = 0; i < 2; i++)
#pragma unroll
                for (int j = 0; j < 2; j++)
                    wmma::mma_sync(acc[i][j], af[i], bf[j], acc[i][j]);
        }
        __syncthreads();
    }

    // stage accumulators to smem (union with As/Bs; safe after final sync)
#pragma unroll
    for (int i = 0; i < 2; i++)
#pragma unroll
        for (int j = 0; j < 2; j++)
            wmma::store_matrix_sync(&Cs[wm*32 + i*16][wn*32 + j*16], acc[i][j], 68, wmma::mem_row_major);
    __syncthreads();

    // epilogue: 8192 elems / 256 threads
#pragma unroll
    for (int l = 0; l < 32; l++) {
        int e = tid + l*256;
        int r = e >> 6, c = e & 63;
        float val = Cs[r][c];
        int grow = row0 + r, gcol = col0 + c;
        if (EPI == EPI_QKV) {
            outH[(size_t)grow*N + gcol] = __float2bfloat16(val);
        } else if (EPI == EPI_PROJ) {
            val += bias[gcol];
            // back-shift: shifted token grow -> unshifted position
            int b  = grow / TOK_IMG;
            int rr = (grow / HW) % HW;
            int cc = grow % HW;
            int drow = b * TOK_IMG + ((rr + 3) % HW) * HW + ((cc + 3) % HW);
            outF[(size_t)drow*DIM + gcol] = resid[(size_t)drow*DIM + gcol] + val;
        } else if (EPI == EPI_MLP1) {
            val += bias[gcol];
            val = 0.5f * val * (1.f + erff(val * 0.7071067811865476f));   // exact GELU
            outH[(size_t)grow*N + gcol] = __float2bfloat16(val);
        } else { // EPI_MLP2
            val += bias[gcol];
            outF[(size_t)grow*DIM + gcol] = resid[(size_t)grow*DIM + gcol] + val;
        }
    }
}

// ---------------- window attention ----------------
// one block per (batch, window); 6 heads processed sequentially
__global__ void __launch_bounds__(256) attn_kernel(
    const __nv_bfloat16* __restrict__ qkv, const float* __restrict__ rbias,
    __nv_bfloat16* __restrict__ outA)
{
    __shared__ __nv_bfloat16 sQ[WS2][34], sK[WS2][34], sV[WS2][34];
    __shared__ float sB[WS2][WS2];
    __shared__ float sD[WS2][50];

    int tid = threadIdx.x;
    int blk = blockIdx.x;
    int b   = blk >> 8;        // / 256
    int w   = blk & 255;
    int wi  = w >> 4, wj = w & 15;
    bool mask_ul = (wi == NWIN - 1);   // bottom row of windows
    bool mask_lr = (wj == NWIN - 1);   // rightmost column of windows

    for (int e = tid; e < WS2*WS2; e += 256) {
        int i = e / WS2, j = e % WS2;
        float m = rbias[e];
        if (mask_ul && ((i >= 28) != (j >= 28)))             m -= 1e9f;
        if (mask_lr && (((i % 7) >= 4) != ((j % 7) >= 4)))   m -= 1e9f;
        sB[i][j] = m;
    }

    int base = (b * HW + wi * WS) * HW + wj * WS;   // token of window's (0,0)

    for (int h = 0; h < HEADS; h++) {
        for (int e = tid; e < WS2*HD; e += 256) {
            int i = e >> 5, d = e & 31;
            int t = base + (i / WS) * HW + (i % WS);
            const __nv_bfloat16* p = qkv + (size_t)t*576 + h*HD + d;
            sQ[i][d] = p[0];
            sK[i][d] = p[192];
            sV[i][d] = p[384];
        }
        __syncthreads();

        for (int e = tid; e < WS2*WS2; e += 256) {
            int i = e / WS2, j = e % WS2;
            float s = 0.f;
#pragma unroll
            for (int d = 0; d < HD; d++)
                s += __bfloat162float(sQ[i][d]) * __bfloat162float(sK[j][d]);
            sD[i][j] = s * 0.17677669529663689f + sB[i][j];
        }
        __syncthreads();

        if (tid < WS2) {
            float mx = -1e30f;
            for (int j = 0; j < WS2; j++) mx = fmaxf(mx, sD[tid][j]);
            float sum = 0.f;
            for (int j = 0; j < WS2; j++) {
                float ev = __expf(sD[tid][j] - mx);
                sD[tid][j] = ev;
                sum += ev;
            }
            float inv = 1.f / sum;
            for (int j = 0; j < WS2; j++) sD[tid][j] *= inv;
        }
        __syncthreads();

        for (int e = tid; e < WS2*HD; e += 256) {
            int i = e >> 5, d = e & 31;
            float s = 0.f;
#pragma unroll
            for (int j = 0; j < WS2; j++)
                s += sD[i][j] * __bfloat162float(sV[j][d]);
            int t = base + (i / WS) * HW + (i % WS);
            outA[(size_t)t*INNER + h*HD + d] = __float2bfloat16(s);
        }
        __syncthreads();
    }
}

// ---------------- launch ----------------
extern "C" void kernel_launch(void* const* d_in, const int* in_sizes, int n_in,
                              void* d_out, int out_size)
{
    const float* x      = (const float*)d_in[0];
    const float* w_qkv  = (const float*)d_in[1];
    const float* w_out  = (const float*)d_in[2];
    const float* b_out  = (const float*)d_in[3];
    const float* pos    = (const float*)d_in[4];
    const float* ln1_g  = (const float*)d_in[5];
    const float* ln1_b  = (const float*)d_in[6];
    const float* ln2_g  = (const float*)d_in[7];
    const float* ln2_b  = (const float*)d_in[8];
    const float* w1     = (const float*)d_in[9];
    const float* b1     = (const float*)d_in[10];
    const float* w2     = (const float*)d_in[11];
    const float* b2     = (const float*)d_in[12];
    float* out = (float*)d_out;

    void *p_y, *p_qkv, *p_attn, *p_x2, *p_h, *p_mlp;
    void *p_wqkv, *p_wout, *p_w1, *p_w2, *p_bias;
    cudaGetSymbolAddress(&p_y,    g_y);
    cudaGetSymbolAddress(&p_qkv,  g_qkv);
    cudaGetSymbolAddress(&p_attn, g_attn);
    cudaGetSymbolAddress(&p_x2,   g_x2);
    cudaGetSymbolAddress(&p_h,    g_h);
    cudaGetSymbolAddress(&p_mlp,  g_mlp);
    cudaGetSymbolAddress(&p_wqkv, g_wqkv);
    cudaGetSymbolAddress(&p_wout, g_wout);
    cudaGetSymbolAddress(&p_w1,   g_w1);
    cudaGetSymbolAddress(&p_w2,   g_w2);
    cudaGetSymbolAddress(&p_bias, g_bias);

    // weight conversion + bias table
    f2bf_kernel<<<(DIM*576 + 255)/256, 256>>>(w_qkv, (__nv_bfloat16*)p_wqkv, DIM*576);
    f2bf_kernel<<<(INNER*DIM + 255)/256, 256>>>(w_out, (__nv_bfloat16*)p_wout, INNER*DIM);
    f2bf_kernel<<<(DIM*MLPD + 255)/256, 256>>>(w1, (__nv_bfloat16*)p_w1, DIM*MLPD);
    f2bf_kernel<<<(MLPD*DIM + 255)/256, 256>>>(w2, (__nv_bfloat16*)p_w2, MLPD*DIM);
    relbias_kernel<<<1, 256>>>(pos, (float*)p_bias);

    // LN1 (with cyclic -3 shift fused into the read)
    ln_kernel<<<TOKENS/8, 256>>>(x, ln1_g, ln1_b, (__nv_bfloat16*)p_y, 1);

    // QKV gemm: [100352,192]x[192,576]
    gemm_bf16<EPI_QKV><<<dim3(576/64, TOKENS/128), 256>>>(
        (const __nv_bfloat16*)p_y, (const __nv_bfloat16*)p_wqkv, DIM, 576,
        nullptr, nullptr, nullptr, (__nv_bfloat16*)p_qkv);

    // windowed attention
    attn_kernel<<<BATCH*NWIN*NWIN, 256>>>(
        (const __nv_bfloat16*)p_qkv, (const float*)p_bias, (__nv_bfloat16*)p_attn);

    // out-proj + back-shift + residual -> x2 (fp32)
    gemm_bf16<EPI_PROJ><<<dim3(DIM/64, TOKENS/128), 256>>>(
        (const __nv_bfloat16*)p_attn, (const __nv_bfloat16*)p_wout, INNER, DIM,
        b_out, x, (float*)p_x2, nullptr);

    // LN2
    ln_kernel<<<TOKENS/8, 256>>>((const float*)p_x2, ln2_g, ln2_b, (__nv_bfloat16*)p_h, 0);

    // MLP1 + exact GELU
    gemm_bf16<EPI_MLP1><<<dim3(MLPD/64, TOKENS/128), 256>>>(
        (const __nv_bfloat16*)p_h, (const __nv_bfloat16*)p_w1, DIM, MLPD,
        b1, nullptr, nullptr, (__nv_bfloat16*)p_mlp);

    // MLP2 + residual -> out
    gemm_bf16<EPI_MLP2><<<dim3(DIM/64, TOKENS/128), 256>>>(
        (const __nv_bfloat16*)p_mlp, (const __nv_bfloat16*)p_w2, MLPD, DIM,
        b2, (const float*)p_x2, out, nullptr);
}

// round 2
// speedup vs baseline: 1.5034x; 1.5034x over previous
#include <cuda_runtime.h>
#include <cuda_bf16.h>
#include <mma.h>

using namespace nvcuda;

// ---------------- problem constants ----------------
#define BATCH   8
#define HW      112
#define DIM     192
#define HEADS   6
#define HD      32
#define INNER   192
#define MLPD    768
#define WS      7
#define WS2     49
#define NWIN    16
#define TOKENS  (BATCH*HW*HW)        // 100352
#define TOK_IMG (HW*HW)              // 12544

// ---------------- scratch ----------------
__device__ __nv_bfloat16 g_y   [(size_t)TOKENS*DIM];
__device__ __nv_bfloat16 g_qkv [(size_t)TOKENS*576];
__device__ __nv_bfloat16 g_attn[(size_t)TOKENS*INNER];
__device__ float         g_x2  [(size_t)TOKENS*DIM];
__device__ __nv_bfloat16 g_h   [(size_t)TOKENS*DIM];
__device__ __nv_bfloat16 g_mlp [(size_t)TOKENS*MLPD];
__device__ __nv_bfloat16 g_wqkv[DIM*576];
__device__ __nv_bfloat16 g_wout[INNER*DIM];
__device__ __nv_bfloat16 g_w1  [DIM*MLPD];
__device__ __nv_bfloat16 g_w2  [MLPD*DIM];
__device__ float         g_bias[WS2*WS2];

// ---------------- cp.async helpers ----------------
__device__ __forceinline__ void cp16(void* s, const void* g) {
    unsigned sa = (unsigned)__cvta_generic_to_shared(s);
    asm volatile("cp.async.cg.shared.global [%0], [%1], 16;\n" :: "r"(sa), "l"(g));
}
__device__ __forceinline__ void cp_commit() { asm volatile("cp.async.commit_group;\n"); }
template<int N> __device__ __forceinline__ void cp_wait() {
    asm volatile("cp.async.wait_group %0;\n" :: "n"(N));
}

// ---------------- fused weight convert + rel-bias ----------------
#define SZ_QKV (DIM*576)
#define SZ_OUT (INNER*DIM)
#define SZ_W1  (DIM*MLPD)
#define SZ_W2  (MLPD*DIM)
#define SZ_ALL (SZ_QKV+SZ_OUT+SZ_W1+SZ_W2)
__global__ void convert_kernel(
    const float* __restrict__ wqkv, const float* __restrict__ wout,
    const float* __restrict__ w1, const float* __restrict__ w2,
    const float* __restrict__ pos,
    __nv_bfloat16* __restrict__ o_qkv, __nv_bfloat16* __restrict__ o_out,
    __nv_bfloat16* __restrict__ o_w1, __nv_bfloat16* __restrict__ o_w2,
    float* __restrict__ bias)
{
    int i = blockIdx.x * blockDim.x + threadIdx.x;
    if (i < SZ_QKV) { o_qkv[i] = __float2bfloat16(wqkv[i]); return; }
    i -= SZ_QKV;
    if (i < SZ_OUT) { o_out[i] = __float2bfloat16(wout[i]); return; }
    i -= SZ_OUT;
    if (i < SZ_W1)  { o_w1[i] = __float2bfloat16(w1[i]); return; }
    i -= SZ_W1;
    if (i < SZ_W2)  { o_w2[i] = __float2bfloat16(w2[i]); return; }
    i -= SZ_W2;
    if (i < WS2*WS2) {
        int r = i / WS2, c = i % WS2;
        int ri = r / WS, ci = r % WS, rj = c / WS, cj = c % WS;
        bias[i] = pos[(ri - rj + WS - 1) * (2*WS - 1) + (ci - cj + WS - 1)];
    }
}

// ---------------- LayerNorm (optional fused -3 cyclic shift) ----------------
__global__ void __launch_bounds__(256) ln_kernel(
    const float* __restrict__ in, const float* __restrict__ gam,
    const float* __restrict__ bet, __nv_bfloat16* __restrict__ out, int shift)
{
    int warp = (blockIdx.x * blockDim.x + threadIdx.x) >> 5;
    int lane = threadIdx.x & 31;
    if (warp >= TOKENS) return;
    int t = warp;
    size_t src;
    if (shift) {
        int b = t / TOK_IMG;
        int r = (t / HW) % HW;
        int c = t % HW;
        src = (size_t)(b * TOK_IMG + ((r + 3) % HW) * HW + ((c + 3) % HW)) * DIM;
    } else {
        src = (size_t)t * DIM;
    }
    float v[6];
    float s = 0.f, sq = 0.f;
#pragma unroll
    for (int k = 0; k < 6; k++) {
        v[k] = in[src + lane + 32*k];
        s += v[k]; sq += v[k]*v[k];
    }
#pragma unroll
    for (int o = 16; o > 0; o >>= 1) {
        s  += __shfl_xor_sync(0xffffffffu, s,  o);
        sq += __shfl_xor_sync(0xffffffffu, sq, o);
    }
    float mean = s * (1.f/DIM);
    float var  = sq * (1.f/DIM) - mean*mean;
    float rstd = rsqrtf(var + 1e-5f);
    size_t dst = (size_t)t * DIM;
#pragma unroll
    for (int k = 0; k < 6; k++) {
        int c = lane + 32*k;
        out[dst + c] = __float2bfloat16((v[k] - mean) * rstd * gam[c] + bet[c]);
    }
}

// ---------------- GEMM: 256x64 tile, K-tile 64, 2-stage cp.async ----------------
enum { EPI_QKV = 0, EPI_PROJ = 1, EPI_MLP1 = 2, EPI_MLP2 = 3 };

#define A_STRIDE 72
#define STAGE_A  (256*A_STRIDE)             // bf16 elems
#define STAGE_B  (64*A_STRIDE)
#define STAGE_EL (STAGE_A + STAGE_B)        // 23040 elems
#define STAGE_BY (STAGE_EL*2)               // 46080 bytes
#define GEMM_SMEM (2*STAGE_BY)              // 92160 bytes

template<int EPI>
__global__ void __launch_bounds__(256) gemm_bf16(
    const __nv_bfloat16* __restrict__ A, const __nv_bfloat16* __restrict__ B,
    int K, int N,
    const float* __restrict__ bias, const float* __restrict__ resid,
    float* __restrict__ outF, __nv_bfloat16* __restrict__ outH)
{
    extern __shared__ __align__(16) unsigned char smem[];
    int tid  = threadIdx.x;
    int warp = tid >> 5;
    int wm   = warp >> 1;   // 0..3 : 64-row strip
    int wn   = warp & 1;    // 0..1 : 32-col strip
    int row0 = blockIdx.y * 256;
    int col0 = blockIdx.x * 64;

    wmma::fragment<wmma::accumulator,16,16,16,float> acc[4][2];
#pragma unroll
    for (int i = 0; i < 4; i++)
#pragma unroll
        for (int j = 0; j < 2; j++) wmma::fill_fragment(acc[i][j], 0.f);

    auto loadStage = [&](int kb, int s) {
        __nv_bfloat16* As = (__nv_bfloat16*)(smem + (size_t)s * STAGE_BY);
        __nv_bfloat16* Bs = As + STAGE_A;
#pragma unroll
        for (int l = 0; l < 8; l++) {               // 2048 chunks of 16B for A
            int v = tid + l*256;
            int r = v >> 3, c = (v & 7) * 8;
            cp16(&As[r*A_STRIDE + c], A + (size_t)(row0 + r)*K + kb + c);
        }
#pragma unroll
        for (int l = 0; l < 2; l++) {               // 512 chunks for B
            int v = tid + l*256;
            int r = v >> 3, c = (v & 7) * 8;
            cp16(&Bs[r*A_STRIDE + c], B + (size_t)(kb + r)*N + col0 + c);
        }
        cp_commit();
    };

    int nk = K >> 6;
    loadStage(0, 0);
    for (int kb = 0; kb < nk; kb++) {
        if (kb + 1 < nk) { loadStage((kb + 1) << 6, (kb + 1) & 1); cp_wait<1>(); }
        else             { cp_wait<0>(); }
        __syncthreads();
        __nv_bfloat16* As = (__nv_bfloat16*)(smem + (size_t)(kb & 1) * STAGE_BY);
        __nv_bfloat16* Bs = As + STAGE_A;
#pragma unroll
        for (int kk = 0; kk < 64; kk += 16) {
            wmma::fragment<wmma::matrix_a,16,16,16,__nv_bfloat16,wmma::row_major> af[4];
            wmma::fragment<wmma::matrix_b,16,16,16,__nv_bfloat16,wmma::row_major> bfr[2];
#pragma unroll
            for (int i = 0; i < 4; i++)
                wmma::load_matrix_sync(af[i], &As[(wm*64 + i*16)*A_STRIDE + kk], A_STRIDE);
#pragma unroll
            for (int j = 0; j < 2; j++)
                wmma::load_matrix_sync(bfr[j], &Bs[kk*A_STRIDE + wn*32 + j*16], A_STRIDE);
#pragma unroll
            for (int i = 0; i < 4; i++)
#pragma unroll
                for (int j = 0; j < 2; j++)
                    wmma::mma_sync(acc[i][j], af[i], bfr[j], acc[i][j]);
        }
        __syncthreads();
    }

    // epilogue: stage fp32 into smem (aliases stages; safe after final sync)
    float* Cs = (float*)smem;                         // [256][68]
#pragma unroll
    for (int i = 0; i < 4; i++)
#pragma unroll
        for (int j = 0; j < 2; j++)
            wmma::store_matrix_sync(&Cs[(wm*64 + i*16)*68 + wn*32 + j*16], acc[i][j], 68, wmma::mem_row_major);
    __syncthreads();

#pragma unroll
    for (int l = 0; l < 16; l++) {
        int e  = tid + l*256;                         // 4096 float4 groups
        int r  = e >> 4;
        int cg = (e & 15) * 4;
        float4 v = *(float4*)&Cs[r*68 + cg];
        int grow = row0 + r, gcol = col0 + cg;
        if (EPI == EPI_QKV) {
            __nv_bfloat162 h0 = __floats2bfloat162_rn(v.x, v.y);
            __nv_bfloat162 h1 = __floats2bfloat162_rn(v.z, v.w);
            uint2 pk = make_uint2(*(unsigned*)&h0, *(unsigned*)&h1);
            *(uint2*)&outH[(size_t)grow*N + gcol] = pk;
        } else if (EPI == EPI_PROJ) {
            float4 bb = *(const float4*)(bias + gcol);
            int b  = grow / TOK_IMG;
            int rr = (grow / HW) % HW;
            int cc = grow % HW;
            int drow = b * TOK_IMG + ((rr + 3) % HW) * HW + ((cc + 3) % HW);
            float4 rs = *(const float4*)(resid + (size_t)drow*DIM + gcol);
            v.x += bb.x + rs.x; v.y += bb.y + rs.y; v.z += bb.z + rs.z; v.w += bb.w + rs.w;
            *(float4*)(outF + (size_t)drow*DIM + gcol) = v;
        } else if (EPI == EPI_MLP1) {
            float4 bb = *(const float4*)(bias + gcol);
            v.x += bb.x; v.y += bb.y; v.z += bb.z; v.w += bb.w;
            v.x = 0.5f*v.x*(1.f + erff(v.x*0.7071067811865476f));
            v.y = 0.5f*v.y*(1.f + erff(v.y*0.7071067811865476f));
            v.z = 0.5f*v.z*(1.f + erff(v.z*0.7071067811865476f));
            v.w = 0.5f*v.w*(1.f + erff(v.w*0.7071067811865476f));
            __nv_bfloat162 h0 = __floats2bfloat162_rn(v.x, v.y);
            __nv_bfloat162 h1 = __floats2bfloat162_rn(v.z, v.w);
            uint2 pk = make_uint2(*(unsigned*)&h0, *(unsigned*)&h1);
            *(uint2*)&outH[(size_t)grow*N + gcol] = pk;
        } else { // EPI_MLP2
            float4 bb = *(const float4*)(bias + gcol);
            float4 rs = *(const float4*)(resid + (size_t)grow*DIM + gcol);
            v.x += bb.x + rs.x; v.y += bb.y + rs.y; v.z += bb.z + rs.z; v.w += bb.w + rs.w;
            *(float4*)(outF + (size_t)grow*DIM + gcol) = v;
        }
    }
}

// ---------------- window attention (WMMA, block per batch/window/head) ----------------
__global__ void __launch_bounds__(128) attn_kernel(
    const __nv_bfloat16* __restrict__ qkv, const float* __restrict__ rbias,
    __nv_bfloat16* __restrict__ outA)
{
    __shared__ __nv_bfloat16 sQ[64][40], sK[64][40], sV[64][40];
    __shared__ float sSc[64][68];
    __shared__ __nv_bfloat16 sP[64][72];

    int tid = threadIdx.x;
    int w   = tid >> 5;
    int h   = blockIdx.x;
    int win = blockIdx.y;
    int b   = blockIdx.z;
    int wi  = win >> 4, wj = win & 15;
    bool mul = (wi == NWIN - 1);
    bool mlr = (wj == NWIN - 1);
    int base = (b * HW + wi * WS) * HW + wj * WS;

    // zero padding rows 49..63 (cols 0..31) of Q,K,V
    {
        uint4 z = make_uint4(0,0,0,0);
        __nv_bfloat16* mats[3] = {&sQ[0][0], &sK[0][0], &sV[0][0]};
        for (int e = tid; e < 180; e += 128) {
            int m = e / 60, rem = e % 60;
            int rr = 49 + (rem >> 2), ch = rem & 3;
            *(uint4*)&mats[m][rr*40 + ch*8] = z;
        }
    }
    // load 49 rows of Q,K,V (uint4 = 8 bf16 per chunk, 4 chunks/row)
    for (int e = tid; e < 196; e += 128) {
        int i = e >> 2, ch = e & 3;
        int t = base + (i / WS) * HW + (i % WS);
        const __nv_bfloat16* p = qkv + (size_t)t*576 + h*HD + ch*8;
        *(uint4*)&sQ[i][ch*8] = *(const uint4*)(p);
        *(uint4*)&sK[i][ch*8] = *(const uint4*)(p + 192);
        *(uint4*)&sV[i][ch*8] = *(const uint4*)(p + 384);
    }
    __syncthreads();

    // QK^T: each warp computes a 16x64 strip
    {
        wmma::fragment<wmma::accumulator,16,16,16,float> c[4];
#pragma unroll
        for (int j = 0; j < 4; j++) wmma::fill_fragment(c[j], 0.f);
#pragma unroll
        for (int kk = 0; kk < 32; kk += 16) {
            wmma::fragment<wmma::matrix_a,16,16,16,__nv_bfloat16,wmma::row_major> a;
            wmma::load_matrix_sync(a, &sQ[w*16][kk], 40);
#pragma unroll
            for (int j = 0; j < 4; j++) {
                wmma::fragment<wmma::matrix_b,16,16,16,__nv_bfloat16,wmma::col_major> bfr;
                wmma::load_matrix_sync(bfr, &sK[j*16][kk], 40);
                wmma::mma_sync(c[j], a, bfr, c[j]);
            }
        }
#pragma unroll
        for (int j = 0; j < 4; j++)
            wmma::store_matrix_sync(&sSc[w*16][j*16], c[j], 68, wmma::mem_row_major);
    }
    __syncthreads();

    // scale + rel bias + shift masks + pad masking
    for (int e = tid; e < 4096; e += 128) {
        int i = e >> 6, j = e & 63;
        float v;
        if (j >= WS2) v = -1e9f;
        else if (i < WS2) {
            v = sSc[i][j] * 0.17677669529663689f + rbias[i*WS2 + j];
            if (mul && ((i >= 28) != (j >= 28)))           v -= 1e9f;
            if (mlr && (((i % 7) >= 4) != ((j % 7) >= 4))) v -= 1e9f;
        } else v = 0.f;
        sSc[i][j] = v;
    }
    __syncthreads();

    // softmax: thread per row (rows 0..48)
    if (tid < WS2) {
        float mx = -1e30f;
        for (int j = 0; j < 64; j++) mx = fmaxf(mx, sSc[tid][j]);
        float sum = 0.f;
        for (int j = 0; j < 64; j++) {
            float ev = __expf(sSc[tid][j] - mx);
            sSc[tid][j] = ev;
            sum += ev;
        }
        float inv = 1.f / sum;
        for (int j = 0; j < 64; j++) sSc[tid][j] *= inv;
    }
    __syncthreads();

    // convert probs to bf16 (zero pad rows)
    for (int e = tid; e < 4096; e += 128) {
        int i = e >> 6, j = e & 63;
        sP[i][j] = (i < WS2) ? __float2bfloat16(sSc[i][j]) : __float2bfloat16(0.f);
    }
    __syncthreads();

    // AV: each warp computes 16x32 strip
    float* so = &sSc[0][0];   // reuse as [64][36]
    {
        wmma::fragment<wmma::accumulator,16,16,16,float> c2[2];
#pragma unroll
        for (int j = 0; j < 2; j++) wmma::fill_fragment(c2[j], 0.f);
#pragma unroll
        for (int kk = 0; kk < 64; kk += 16) {
            wmma::fragment<wmma::matrix_a,16,16,16,__nv_bfloat16,wmma::row_major> a;
            wmma::load_matrix_sync(a, &sP[w*16][kk], 72);
#pragma unroll
            for (int j = 0; j < 2; j++) {
                wmma::fragment<wmma::matrix_b,16,16,16,__nv_bfloat16,wmma::row_major> bfr;
                wmma::load_matrix_sync(bfr, &sV[kk][j*16], 40);
                wmma::mma_sync(c2[j], a, bfr, c2[j]);
            }
        }
        __syncthreads();   // sSc fully read before overwrite
#pragma unroll
        for (int j = 0; j < 2; j++)
            wmma::store_matrix_sync(&so[(w*16)*36 + j*16], c2[j], 36, wmma::mem_row_major);
    }
    __syncthreads();

    // write 49x32 outputs (bf16x2)
    for (int e = tid; e < WS2*16; e += 128) {
        int i = e >> 4, d2 = (e & 15) * 2;
        int t = base + (i / WS) * HW + (i % WS);
        __nv_bfloat162 pr = __floats2bfloat162_rn(so[i*36 + d2], so[i*36 + d2 + 1]);
        *(__nv_bfloat162*)&outA[(size_t)t*INNER + h*HD + d2] = pr;
    }
}

// ---------------- launch ----------------
extern "C" void kernel_launch(void* const* d_in, const int* in_sizes, int n_in,
                              void* d_out, int out_size)
{
    const float* x      = (const float*)d_in[0];
    const float* w_qkv  = (const float*)d_in[1];
    const float* w_out  = (const float*)d_in[2];
    const float* b_out  = (const float*)d_in[3];
    const float* pos    = (const float*)d_in[4];
    const float* ln1_g  = (const float*)d_in[5];
    const float* ln1_b  = (const float*)d_in[6];
    const float* ln2_g  = (const float*)d_in[7];
    const float* ln2_b  = (const float*)d_in[8];
    const float* w1     = (const float*)d_in[9];
    const float* b1     = (const float*)d_in[10];
    const float* w2     = (const float*)d_in[11];
    const float* b2     = (const float*)d_in[12];
    float* out = (float*)d_out;

    void *p_y, *p_qkv, *p_attn, *p_x2, *p_h, *p_mlp;
    void *p_wqkv, *p_wout, *p_w1, *p_w2, *p_bias;
    cudaGetSymbolAddress(&p_y,    g_y);
    cudaGetSymbolAddress(&p_qkv,  g_qkv);
    cudaGetSymbolAddress(&p_attn, g_attn);
    cudaGetSymbolAddress(&p_x2,   g_x2);
    cudaGetSymbolAddress(&p_h,    g_h);
    cudaGetSymbolAddress(&p_mlp,  g_mlp);
    cudaGetSymbolAddress(&p_wqkv, g_wqkv);
    cudaGetSymbolAddress(&p_wout, g_wout);
    cudaGetSymbolAddress(&p_w1,   g_w1);
    cudaGetSymbolAddress(&p_w2,   g_w2);
    cudaGetSymbolAddress(&p_bias, g_bias);

    static bool attr_done = false;
    if (!attr_done) {
        cudaFuncSetAttribute(gemm_bf16<EPI_QKV>,  cudaFuncAttributeMaxDynamicSharedMemorySize, GEMM_SMEM);
        cudaFuncSetAttribute(gemm_bf16<EPI_PROJ>, cudaFuncAttributeMaxDynamicSharedMemorySize, GEMM_SMEM);
        cudaFuncSetAttribute(gemm_bf16<EPI_MLP1>, cudaFuncAttributeMaxDynamicSharedMemorySize, GEMM_SMEM);
        cudaFuncSetAttribute(gemm_bf16<EPI_MLP2>, cudaFuncAttributeMaxDynamicSharedMemorySize, GEMM_SMEM);
        attr_done = true;
    }

    // weights -> bf16, rel-bias table (single launch)
    convert_kernel<<<(SZ_ALL + WS2*WS2 + 255)/256, 256>>>(
        w_qkv, w_out, w1, w2, pos,
        (__nv_bfloat16*)p_wqkv, (__nv_bfloat16*)p_wout,
        (__nv_bfloat16*)p_w1, (__nv_bfloat16*)p_w2, (float*)p_bias);

    // LN1 with -3 cyclic shift
    ln_kernel<<<TOKENS/8, 256>>>(x, ln1_g, ln1_b, (__nv_bfloat16*)p_y, 1);

    // QKV: [100352,192] x [192,576]
    gemm_bf16<EPI_QKV><<<dim3(576/64, TOKENS/256), 256, GEMM_SMEM>>>(
        (const __nv_bfloat16*)p_y, (const __nv_bfloat16*)p_wqkv, DIM, 576,
        nullptr, nullptr, nullptr, (__nv_bfloat16*)p_qkv);

    // windowed attention
    attn_kernel<<<dim3(HEADS, NWIN*NWIN, BATCH), 128>>>(
        (const __nv_bfloat16*)p_qkv, (const float*)p_bias, (__nv_bfloat16*)p_attn);

    // out-proj + back-shift + residual
    gemm_bf16<EPI_PROJ><<<dim3(DIM/64, TOKENS/256), 256, GEMM_SMEM>>>(
        (const __nv_bfloat16*)p_attn, (const __nv_bfloat16*)p_wout, INNER, DIM,
        b_out, x, (float*)p_x2, nullptr);

    // LN2
    ln_kernel<<<TOKENS/8, 256>>>((const float*)p_x2, ln2_g, ln2_b, (__nv_bfloat16*)p_h, 0);

    // MLP1 + exact GELU
    gemm_bf16<EPI_MLP1><<<dim3(MLPD/64, TOKENS/256), 256, GEMM_SMEM>>>(
        (const __nv_bfloat16*)p_h, (const __nv_bfloat16*)p_w1, DIM, MLPD,
        b1, nullptr, nullptr, (__nv_bfloat16*)p_mlp);

    // MLP2 + residual -> out
    gemm_bf16<EPI_MLP2><<<dim3(DIM/64, TOKENS/256), 256, GEMM_SMEM>>>(
        (const __nv_bfloat16*)p_mlp, (const __nv_bfloat16*)p_w2, MLPD, DIM,
        b2, (const float*)p_x2, out, nullptr);
}

// round 3
// speedup vs baseline: 1.5524x; 1.0326x over previous
#include <cuda_runtime.h>
#include <cuda_bf16.h>
#include <mma.h>

using namespace nvcuda;

// ---------------- problem constants ----------------
#define BATCH   8
#define HW      112
#define DIM     192
#define HEADS   6
#define HD      32
#define INNER   192
#define MLPD    768
#define WS      7
#define WS2     49
#define NWIN    16
#define TOKENS  (BATCH*HW*HW)        // 100352
#define TOK_IMG (HW*HW)              // 12544

// ---------------- scratch ----------------
__device__ __nv_bfloat16 g_y   [(size_t)TOKENS*DIM];
__device__ __nv_bfloat16 g_qkv [(size_t)TOKENS*576];
__device__ __nv_bfloat16 g_attn[(size_t)TOKENS*INNER];
__device__ float         g_x2  [(size_t)TOKENS*DIM];
__device__ __nv_bfloat16 g_h   [(size_t)TOKENS*DIM];
__device__ __nv_bfloat16 g_mlp [(size_t)TOKENS*MLPD];
__device__ __nv_bfloat16 g_wqkv[DIM*576];
__device__ __nv_bfloat16 g_wout[INNER*DIM];
__device__ __nv_bfloat16 g_w1  [DIM*MLPD];
__device__ __nv_bfloat16 g_w2  [MLPD*DIM];
__device__ float         g_bias[WS2*WS2];

// ---------------- cp.async helpers ----------------
__device__ __forceinline__ void cp16(void* s, const void* g) {
    unsigned sa = (unsigned)__cvta_generic_to_shared(s);
    asm volatile("cp.async.cg.shared.global [%0], [%1], 16;\n" :: "r"(sa), "l"(g));
}
__device__ __forceinline__ void cp_commit() { asm volatile("cp.async.commit_group;\n"); }
template<int N> __device__ __forceinline__ void cp_wait() {
    asm volatile("cp.async.wait_group %0;\n" :: "n"(N));
}

// ---------------- fused weight convert + rel-bias ----------------
#define SZ_QKV (DIM*576)
#define SZ_OUT (INNER*DIM)
#define SZ_W1  (DIM*MLPD)
#define SZ_W2  (MLPD*DIM)
#define SZ_ALL (SZ_QKV+SZ_OUT+SZ_W1+SZ_W2)
__global__ void convert_kernel(
    const float* __restrict__ wqkv, const float* __restrict__ wout,
    const float* __restrict__ w1, const float* __restrict__ w2,
    const float* __restrict__ pos,
    __nv_bfloat16* __restrict__ o_qkv, __nv_bfloat16* __restrict__ o_out,
    __nv_bfloat16* __restrict__ o_w1, __nv_bfloat16* __restrict__ o_w2,
    float* __restrict__ bias)
{
    int i = blockIdx.x * blockDim.x + threadIdx.x;
    if (i < SZ_QKV) { o_qkv[i] = __float2bfloat16(wqkv[i]); return; }
    i -= SZ_QKV;
    if (i < SZ_OUT) { o_out[i] = __float2bfloat16(wout[i]); return; }
    i -= SZ_OUT;
    if (i < SZ_W1)  { o_w1[i] = __float2bfloat16(w1[i]); return; }
    i -= SZ_W1;
    if (i < SZ_W2)  { o_w2[i] = __float2bfloat16(w2[i]); return; }
    i -= SZ_W2;
    if (i < WS2*WS2) {
        int r = i / WS2, c = i % WS2;
        int ri = r / WS, ci = r % WS, rj = c / WS, cj = c % WS;
        bias[i] = pos[(ri - rj + WS - 1) * (2*WS - 1) + (ci - cj + WS - 1)];
    }
}

// ---------------- LayerNorm (optional fused -3 cyclic shift) ----------------
__global__ void __launch_bounds__(256) ln_kernel(
    const float* __restrict__ in, const float* __restrict__ gam,
    const float* __restrict__ bet, __nv_bfloat16* __restrict__ out, int shift)
{
    int warp = (blockIdx.x * blockDim.x + threadIdx.x) >> 5;
    int lane = threadIdx.x & 31;
    if (warp >= TOKENS) return;
    int t = warp;
    size_t src;
    if (shift) {
        int b = t / TOK_IMG;
        int r = (t / HW) % HW;
        int c = t % HW;
        src = (size_t)(b * TOK_IMG + ((r + 3) % HW) * HW + ((c + 3) % HW)) * DIM;
    } else {
        src = (size_t)t * DIM;
    }
    float v[6];
    float s = 0.f, sq = 0.f;
#pragma unroll
    for (int k = 0; k < 6; k++) {
        v[k] = in[src + lane + 32*k];
        s += v[k]; sq += v[k]*v[k];
    }
#pragma unroll
    for (int o = 16; o > 0; o >>= 1) {
        s  += __shfl_xor_sync(0xffffffffu, s,  o);
        sq += __shfl_xor_sync(0xffffffffu, sq, o);
    }
    float mean = s * (1.f/DIM);
    float var  = sq * (1.f/DIM) - mean*mean;
    float rstd = rsqrtf(var + 1e-5f);
    size_t dst = (size_t)t * DIM;
#pragma unroll
    for (int k = 0; k < 6; k++) {
        int c = lane + 32*k;
        out[dst + c] = __float2bfloat16((v[k] - mean) * rstd * gam[c] + bet[c]);
    }
}

// ---------------- GEMM: 256x64 tile, K-tile 64, 2-stage cp.async ----------------
enum { EPI_QKV = 0, EPI_PROJ = 1, EPI_MLP1 = 2, EPI_MLP2 = 3 };

#define A_STRIDE 72
#define STAGE_A  (256*A_STRIDE)
#define STAGE_B  (64*A_STRIDE)
#define STAGE_EL (STAGE_A + STAGE_B)
#define STAGE_BY (STAGE_EL*2)
#define GEMM_SMEM (2*STAGE_BY)

template<int EPI>
__global__ void __launch_bounds__(256) gemm_bf16(
    const __nv_bfloat16* __restrict__ A, const __nv_bfloat16* __restrict__ B,
    int K, int N,
    const float* __restrict__ bias, const float* __restrict__ resid,
    float* __restrict__ outF, __nv_bfloat16* __restrict__ outH)
{
    extern __shared__ __align__(16) unsigned char smem[];
    int tid  = threadIdx.x;
    int warp = tid >> 5;
    int wm   = warp >> 1;
    int wn   = warp & 1;
    int row0 = blockIdx.y * 256;
    int col0 = blockIdx.x * 64;

    wmma::fragment<wmma::accumulator,16,16,16,float> acc[4][2];
#pragma unroll
    for (int i = 0; i < 4; i++)
#pragma unroll
        for (int j = 0; j < 2; j++) wmma::fill_fragment(acc[i][j], 0.f);

    auto loadStage = [&](int kb, int s) {
        __nv_bfloat16* As = (__nv_bfloat16*)(smem + (size_t)s * STAGE_BY);
        __nv_bfloat16* Bs = As + STAGE_A;
#pragma unroll
        for (int l = 0; l < 8; l++) {
            int v = tid + l*256;
            int r = v >> 3, c = (v & 7) * 8;
            cp16(&As[r*A_STRIDE + c], A + (size_t)(row0 + r)*K + kb + c);
        }
#pragma unroll
        for (int l = 0; l < 2; l++) {
            int v = tid + l*256;
            int r = v >> 3, c = (v & 7) * 8;
            cp16(&Bs[r*A_STRIDE + c], B + (size_t)(kb + r)*N + col0 + c);
        }
        cp_commit();
    };

    int nk = K >> 6;
    loadStage(0, 0);
    for (int kb = 0; kb < nk; kb++) {
        if (kb + 1 < nk) { loadStage((kb + 1) << 6, (kb + 1) & 1); cp_wait<1>(); }
        else             { cp_wait<0>(); }
        __syncthreads();
        __nv_bfloat16* As = (__nv_bfloat16*)(smem + (size_t)(kb & 1) * STAGE_BY);
        __nv_bfloat16* Bs = As + STAGE_A;
#pragma unroll
        for (int kk = 0; kk < 64; kk += 16) {
            wmma::fragment<wmma::matrix_a,16,16,16,__nv_bfloat16,wmma::row_major> af[4];
            wmma::fragment<wmma::matrix_b,16,16,16,__nv_bfloat16,wmma::row_major> bfr[2];
#pragma unroll
            for (int i = 0; i < 4; i++)
                wmma::load_matrix_sync(af[i], &As[(wm*64 + i*16)*A_STRIDE + kk], A_STRIDE);
#pragma unroll
            for (int j = 0; j < 2; j++)
                wmma::load_matrix_sync(bfr[j], &Bs[kk*A_STRIDE + wn*32 + j*16], A_STRIDE);
#pragma unroll
            for (int i = 0; i < 4; i++)
#pragma unroll
                for (int j = 0; j < 2; j++)
                    wmma::mma_sync(acc[i][j], af[i], bfr[j], acc[i][j]);
        }
        __syncthreads();
    }

    float* Cs = (float*)smem;
#pragma unroll
    for (int i = 0; i < 4; i++)
#pragma unroll
        for (int j = 0; j < 2; j++)
            wmma::store_matrix_sync(&Cs[(wm*64 + i*16)*68 + wn*32 + j*16], acc[i][j], 68, wmma::mem_row_major);
    __syncthreads();

#pragma unroll
    for (int l = 0; l < 16; l++) {
        int e  = tid + l*256;
        int r  = e >> 4;
        int cg = (e & 15) * 4;
        float4 v = *(float4*)&Cs[r*68 + cg];
        int grow = row0 + r, gcol = col0 + cg;
        if (EPI == EPI_QKV) {
            __nv_bfloat162 h0 = __floats2bfloat162_rn(v.x, v.y);
            __nv_bfloat162 h1 = __floats2bfloat162_rn(v.z, v.w);
            uint2 pk = make_uint2(*(unsigned*)&h0, *(unsigned*)&h1);
            *(uint2*)&outH[(size_t)grow*N + gcol] = pk;
        } else if (EPI == EPI_PROJ) {
            float4 bb = *(const float4*)(bias + gcol);
            int b  = grow / TOK_IMG;
            int rr = (grow / HW) % HW;
            int cc = grow % HW;
            int drow = b * TOK_IMG + ((rr + 3) % HW) * HW + ((cc + 3) % HW);
            float4 rs = *(const float4*)(resid + (size_t)drow*DIM + gcol);
            v.x += bb.x + rs.x; v.y += bb.y + rs.y; v.z += bb.z + rs.z; v.w += bb.w + rs.w;
            *(float4*)(outF + (size_t)drow*DIM + gcol) = v;
        } else if (EPI == EPI_MLP1) {
            float4 bb = *(const float4*)(bias + gcol);
            v.x += bb.x; v.y += bb.y; v.z += bb.z; v.w += bb.w;
            v.x = 0.5f*v.x*(1.f + erff(v.x*0.7071067811865476f));
            v.y = 0.5f*v.y*(1.f + erff(v.y*0.7071067811865476f));
            v.z = 0.5f*v.z*(1.f + erff(v.z*0.7071067811865476f));
            v.w = 0.5f*v.w*(1.f + erff(v.w*0.7071067811865476f));
            __nv_bfloat162 h0 = __floats2bfloat162_rn(v.x, v.y);
            __nv_bfloat162 h1 = __floats2bfloat162_rn(v.z, v.w);
            uint2 pk = make_uint2(*(unsigned*)&h0, *(unsigned*)&h1);
            *(uint2*)&outH[(size_t)grow*N + gcol] = pk;
        } else {
            float4 bb = *(const float4*)(bias + gcol);
            float4 rs = *(const float4*)(resid + (size_t)grow*DIM + gcol);
            v.x += bb.x + rs.x; v.y += bb.y + rs.y; v.z += bb.z + rs.z; v.w += bb.w + rs.w;
            *(float4*)(outF + (size_t)grow*DIM + gcol) = v;
        }
    }
}

// ---------------- window attention v2 ----------------
// block = (head, window, batch), 128 threads / 4 warps.
// smem (32KB): QKV panels + score buffer; probs bf16 aliased over dead Q+K;
// AV output aliased over dead scores. Softmax is warp-per-row with fused
// scale + rel-bias + shift masks and direct bf16 prob writes.
__global__ void __launch_bounds__(128) attn_kernel(
    const __nv_bfloat16* __restrict__ qkv, const float* __restrict__ rbias,
    __nv_bfloat16* __restrict__ outA)
{
    __shared__ __align__(16) unsigned char sm[3*64*40*2 + 64*68*4];
    __nv_bfloat16* sQ = (__nv_bfloat16*)sm;          // [64][40]
    __nv_bfloat16* sK = sQ + 64*40;                  // [64][40]
    __nv_bfloat16* sV = sK + 64*40;                  // [64][40]
    float*         sSc = (float*)(sm + 3*64*40*2);   // [64][68]
    __nv_bfloat16* sP = sQ;                          // [64][72] aliases Q+K (9216<=10240B)
    float*         sO = sSc;                         // [64][36] aliases scores

    int tid = threadIdx.x;
    int w   = tid >> 5;
    int lane = tid & 31;
    int h   = blockIdx.x;
    int win = blockIdx.y;
    int b   = blockIdx.z;
    int wi  = win >> 4, wj = win & 15;
    bool mul = (wi == NWIN - 1);
    bool mlr = (wj == NWIN - 1);
    int base = (b * HW + wi * WS) * HW + wj * WS;

    // zero pad rows 49..63 of Q,K,V (5 uint4 per 40-col row)
    {
        uint4 z = make_uint4(0,0,0,0);
        __nv_bfloat16* mats[3] = {sQ, sK, sV};
        for (int e = tid; e < 225; e += 128) {
            int m = e / 75, rem = e % 75;
            int rr = 49 + rem / 5, ch = rem % 5;
            *(uint4*)&mats[m][rr*40 + ch*8] = z;
        }
    }
    // load 49 rows of Q,K,V
    for (int e = tid; e < 196; e += 128) {
        int i = e >> 2, ch = e & 3;
        int t = base + (i / WS) * HW + (i % WS);
        const __nv_bfloat16* p = qkv + (size_t)t*576 + h*HD + ch*8;
        *(uint4*)&sQ[i*40 + ch*8] = *(const uint4*)(p);
        *(uint4*)&sK[i*40 + ch*8] = *(const uint4*)(p + 192);
        *(uint4*)&sV[i*40 + ch*8] = *(const uint4*)(p + 384);
    }
    __syncthreads();

    // QK^T: each warp one 16x64 strip
    {
        wmma::fragment<wmma::accumulator,16,16,16,float> c[4];
#pragma unroll
        for (int j = 0; j < 4; j++) wmma::fill_fragment(c[j], 0.f);
#pragma unroll
        for (int kk = 0; kk < 32; kk += 16) {
            wmma::fragment<wmma::matrix_a,16,16,16,__nv_bfloat16,wmma::row_major> a;
            wmma::load_matrix_sync(a, &sQ[(w*16)*40 + kk], 40);
#pragma unroll
            for (int j = 0; j < 4; j++) {
                wmma::fragment<wmma::matrix_b,16,16,16,__nv_bfloat16,wmma::col_major> bfr;
                wmma::load_matrix_sync(bfr, &sK[(j*16)*40 + kk], 40);
                wmma::mma_sync(c[j], a, bfr, c[j]);
            }
        }
#pragma unroll
        for (int j = 0; j < 4; j++)
            wmma::store_matrix_sync(&sSc[(w*16)*68 + j*16], c[j], 68, wmma::mem_row_major);
    }
    __syncthreads();

    // fused softmax: warp-per-row (16 rows/warp), 2 cols/lane,
    // scale + rel-bias + shift masks inline, bf16 probs written directly.
    {
        const float SC = 0.17677669529663689f;
        int j2 = lane + 32;
        bool jb1 = (lane >= 28);                 // j2 >= 28 always
        bool j71 = (lane % 7) >= 4;
        bool j72 = (j2 % 7) >= 4;
        bool jv2 = (j2 < WS2);                   // lane < 17
#pragma unroll
        for (int rr = 0; rr < 16; rr++) {
            int i = w*16 + rr;
            if (i < WS2) {
                bool ib = (i >= 28);
                bool i7 = (i % 7) >= 4;
                const float* br = rbias + i*WS2;
                float v1 = sSc[i*68 + lane]*SC + br[lane];
                if (mul && (ib != jb1)) v1 -= 1e9f;
                if (mlr && (i7 != j71)) v1 -= 1e9f;
                float v2 = -1e30f;
                if (jv2) {
                    v2 = sSc[i*68 + j2]*SC + br[j2];
                    if (mul && ib == false) v2 -= mul ? 0.f : 0.f;  // placeholder removed below
                }
                // recompute cleanly (compiler folds):
                if (jv2) {
                    v2 = sSc[i*68 + j2]*SC + br[j2];
                    if (mul && (ib != true)) v2 -= 1e9f;   // jb2 == true
                    if (mlr && (i7 != j72)) v2 -= 1e9f;
                }
                float m = fmaxf(v1, v2);
#pragma unroll
                for (int o = 16; o > 0; o >>= 1)
                    m = fmaxf(m, __shfl_xor_sync(0xffffffffu, m, o));
                float e1 = __expf(v1 - m);
                float e2 = jv2 ? __expf(v2 - m) : 0.f;
                float s = e1 + e2;
#pragma unroll
                for (int o = 16; o > 0; o >>= 1)
                    s += __shfl_xor_sync(0xffffffffu, s, o);
                float inv = 1.f / s;
                sP[i*72 + lane] = __float2bfloat16(e1*inv);
                sP[i*72 + j2]   = __float2bfloat16(e2*inv);
            } else {
                sP[i*72 + lane] = __float2bfloat16(0.f);
                sP[i*72 + j2]   = __float2bfloat16(0.f);
            }
        }
    }
    __syncthreads();

    // AV: each warp 16x32 strip; output into sO (aliases scores, dead now)
    {
        wmma::fragment<wmma::accumulator,16,16,16,float> c2[2];
#pragma unroll
        for (int j = 0; j < 2; j++) wmma::fill_fragment(c2[j], 0.f);
#pragma unroll
        for (int kk = 0; kk < 64; kk += 16) {
            wmma::fragment<wmma::matrix_a,16,16,16,__nv_bfloat16,wmma::row_major> a;
            wmma::load_matrix_sync(a, &sP[(w*16)*72 + kk], 72);
#pragma unroll
            for (int j = 0; j < 2; j++) {
                wmma::fragment<wmma::matrix_b,16,16,16,__nv_bfloat16,wmma::row_major> bfr;
                wmma::load_matrix_sync(bfr, &sV[kk*40 + j*16], 40);
                wmma::mma_sync(c2[j], a, bfr, c2[j]);
            }
        }
#pragma unroll
        for (int j = 0; j < 2; j++)
            wmma::store_matrix_sync(&sO[(w*16)*36 + j*16], c2[j], 36, wmma::mem_row_major);
    }
    __syncthreads();

    // write 49x32 outputs
    for (int e = tid; e < WS2*16; e += 128) {
        int i = e >> 4, d2 = (e & 15) * 2;
        int t = base + (i / WS) * HW + (i % WS);
        __nv_bfloat162 pr = __floats2bfloat162_rn(sO[i*36 + d2], sO[i*36 + d2 + 1]);
        *(__nv_bfloat162*)&outA[(size_t)t*INNER + h*HD + d2] = pr;
    }
}

// ---------------- launch ----------------
extern "C" void kernel_launch(void* const* d_in, const int* in_sizes, int n_in,
                              void* d_out, int out_size)
{
    const float* x      = (const float*)d_in[0];
    const float* w_qkv  = (const float*)d_in[1];
    const float* w_out  = (const float*)d_in[2];
    const float* b_out  = (const float*)d_in[3];
    const float* pos    = (const float*)d_in[4];
    const float* ln1_g  = (const float*)d_in[5];
    const float* ln1_b  = (const float*)d_in[6];
    const float* ln2_g  = (const float*)d_in[7];
    const float* ln2_b  = (const float*)d_in[8];
    const float* w1     = (const float*)d_in[9];
    const float* b1     = (const float*)d_in[10];
    const float* w2     = (const float*)d_in[11];
    const float* b2     = (const float*)d_in[12];
    float* out = (float*)d_out;

    void *p_y, *p_qkv, *p_attn, *p_x2, *p_h, *p_mlp;
    void *p_wqkv, *p_wout, *p_w1, *p_w2, *p_bias;
    cudaGetSymbolAddress(&p_y,    g_y);
    cudaGetSymbolAddress(&p_qkv,  g_qkv);
    cudaGetSymbolAddress(&p_attn, g_attn);
    cudaGetSymbolAddress(&p_x2,   g_x2);
    cudaGetSymbolAddress(&p_h,    g_h);
    cudaGetSymbolAddress(&p_mlp,  g_mlp);
    cudaGetSymbolAddress(&p_wqkv, g_wqkv);
    cudaGetSymbolAddress(&p_wout, g_wout);
    cudaGetSymbolAddress(&p_w1,   g_w1);
    cudaGetSymbolAddress(&p_w2,   g_w2);
    cudaGetSymbolAddress(&p_bias, g_bias);

    static bool attr_done = false;
    if (!attr_done) {
        cudaFuncSetAttribute(gemm_bf16<EPI_QKV>,  cudaFuncAttributeMaxDynamicSharedMemorySize, GEMM_SMEM);
        cudaFuncSetAttribute(gemm_bf16<EPI_PROJ>, cudaFuncAttributeMaxDynamicSharedMemorySize, GEMM_SMEM);
        cudaFuncSetAttribute(gemm_bf16<EPI_MLP1>, cudaFuncAttributeMaxDynamicSharedMemorySize, GEMM_SMEM);
        cudaFuncSetAttribute(gemm_bf16<EPI_MLP2>, cudaFuncAttributeMaxDynamicSharedMemorySize, GEMM_SMEM);
        attr_done = true;
    }

    convert_kernel<<<(SZ_ALL + WS2*WS2 + 255)/256, 256>>>(
        w_qkv, w_out, w1, w2, pos,
        (__nv_bfloat16*)p_wqkv, (__nv_bfloat16*)p_wout,
        (__nv_bfloat16*)p_w1, (__nv_bfloat16*)p_w2, (float*)p_bias);

    ln_kernel<<<TOKENS/8, 256>>>(x, ln1_g, ln1_b, (__nv_bfloat16*)p_y, 1);

    gemm_bf16<EPI_QKV><<<dim3(576/64, TOKENS/256), 256, GEMM_SMEM>>>(
        (const __nv_bfloat16*)p_y, (const __nv_bfloat16*)p_wqkv, DIM, 576,
        nullptr, nullptr, nullptr, (__nv_bfloat16*)p_qkv);

    attn_kernel<<<dim3(HEADS, NWIN*NWIN, BATCH), 128>>>(
        (const __nv_bfloat16*)p_qkv, (const float*)p_bias, (__nv_bfloat16*)p_attn);

    gemm_bf16<EPI_PROJ><<<dim3(DIM/64, TOKENS/256), 256, GEMM_SMEM>>>(
        (const __nv_bfloat16*)p_attn, (const __nv_bfloat16*)p_wout, INNER, DIM,
        b_out, x, (float*)p_x2, nullptr);

    ln_kernel<<<TOKENS/8, 256>>>((const float*)p_x2, ln2_g, ln2_b, (__nv_bfloat16*)p_h, 0);

    gemm_bf16<EPI_MLP1><<<dim3(MLPD/64, TOKENS/256), 256, GEMM_SMEM>>>(
        (const __nv_bfloat16*)p_h, (const __nv_bfloat16*)p_w1, DIM, MLPD,
        b1, nullptr, nullptr, (__nv_bfloat16*)p_mlp);

    gemm_bf16<EPI_MLP2><<<dim3(DIM/64, TOKENS/256), 256, GEMM_SMEM>>>(
        (const __nv_bfloat16*)p_mlp, (const __nv_bfloat16*)p_w2, MLPD, DIM,
        b2, (const float*)p_x2, out, nullptr);
}

// round 4
// speedup vs baseline: 1.8448x; 1.1884x over previous
#include <cuda_runtime.h>
#include <cuda_bf16.h>
#include <mma.h>

using namespace nvcuda;

// ---------------- problem constants ----------------
#define BATCH   8
#define HW      112
#define DIM     192
#define HEADS   6
#define HD      32
#define INNER   192
#define MLPD    768
#define WS      7
#define WS2     49
#define NWIN    16
#define TOKENS  (BATCH*HW*HW)        // 100352
#define TOK_IMG (HW*HW)              // 12544

// ---------------- scratch ----------------
__device__ __nv_bfloat16 g_y   [(size_t)TOKENS*DIM];
__device__ __nv_bfloat16 g_qkv [(size_t)TOKENS*576];
__device__ __nv_bfloat16 g_attn[(size_t)TOKENS*INNER];
__device__ float         g_x2  [(size_t)TOKENS*DIM];
__device__ __nv_bfloat16 g_h   [(size_t)TOKENS*DIM];
__device__ __nv_bfloat16 g_mlp [(size_t)TOKENS*MLPD];
__device__ __nv_bfloat16 g_wqkv[DIM*576];
__device__ __nv_bfloat16 g_wout[INNER*DIM];
__device__ __nv_bfloat16 g_w1  [DIM*MLPD];
__device__ __nv_bfloat16 g_w2  [MLPD*DIM];
__device__ float         g_bias2[64*64];             // padded rel-bias table

// ---------------- cp.async helpers ----------------
__device__ __forceinline__ void cp16(void* s, const void* g) {
    unsigned sa = (unsigned)__cvta_generic_to_shared(s);
    asm volatile("cp.async.cg.shared.global [%0], [%1], 16;\n" :: "r"(sa), "l"(g));
}
__device__ __forceinline__ void cp_commit() { asm volatile("cp.async.commit_group;\n"); }
template<int N> __device__ __forceinline__ void cp_wait() {
    asm volatile("cp.async.wait_group %0;\n" :: "n"(N));
}

// ---------------- mma / ldmatrix helpers ----------------
__device__ __forceinline__ void ldsm4(unsigned* r, const void* p) {
    unsigned a = (unsigned)__cvta_generic_to_shared(p);
    asm volatile("ldmatrix.sync.aligned.m8n8.x4.shared.b16 {%0,%1,%2,%3}, [%4];\n"
        : "=r"(r[0]),"=r"(r[1]),"=r"(r[2]),"=r"(r[3]) : "r"(a));
}
__device__ __forceinline__ void ldsm4t(unsigned* r, const void* p) {
    unsigned a = (unsigned)__cvta_generic_to_shared(p);
    asm volatile("ldmatrix.sync.aligned.m8n8.x4.trans.shared.b16 {%0,%1,%2,%3}, [%4];\n"
        : "=r"(r[0]),"=r"(r[1]),"=r"(r[2]),"=r"(r[3]) : "r"(a));
}
__device__ __forceinline__ void mma16816(float* d, const unsigned* a, const unsigned* b) {
    asm volatile("mma.sync.aligned.m16n8k16.row.col.f32.bf16.bf16.f32 "
        "{%0,%1,%2,%3}, {%4,%5,%6,%7}, {%8,%9}, {%0,%1,%2,%3};\n"
        : "+f"(d[0]),"+f"(d[1]),"+f"(d[2]),"+f"(d[3])
        : "r"(a[0]),"r"(a[1]),"r"(a[2]),"r"(a[3]), "r"(b[0]),"r"(b[1]));
}

// ---------------- fused weight convert + padded rel-bias ----------------
#define SZ_QKV (DIM*576)
#define SZ_OUT (INNER*DIM)
#define SZ_W1  (DIM*MLPD)
#define SZ_W2  (MLPD*DIM)
#define SZ_ALL (SZ_QKV+SZ_OUT+SZ_W1+SZ_W2)
__global__ void convert_kernel(
    const float* __restrict__ wqkv, const float* __restrict__ wout,
    const float* __restrict__ w1, const float* __restrict__ w2,
    const float* __restrict__ pos,
    __nv_bfloat16* __restrict__ o_qkv, __nv_bfloat16* __restrict__ o_out,
    __nv_bfloat16* __restrict__ o_w1, __nv_bfloat16* __restrict__ o_w2,
    float* __restrict__ bias2)
{
    int i = blockIdx.x * blockDim.x + threadIdx.x;
    if (i < SZ_QKV) { o_qkv[i] = __float2bfloat16(wqkv[i]); return; }
    i -= SZ_QKV;
    if (i < SZ_OUT) { o_out[i] = __float2bfloat16(wout[i]); return; }
    i -= SZ_OUT;
    if (i < SZ_W1)  { o_w1[i] = __float2bfloat16(w1[i]); return; }
    i -= SZ_W1;
    if (i < SZ_W2)  { o_w2[i] = __float2bfloat16(w2[i]); return; }
    i -= SZ_W2;
    if (i < 64*64) {
        int r = i >> 6, c = i & 63;
        float v = 0.f;
        if (r < WS2 && c < WS2) {
            int ri = r / WS, ci = r % WS, rj = c / WS, cj = c % WS;
            v = pos[(ri - rj + WS - 1) * (2*WS - 1) + (ci - cj + WS - 1)];
        }
        bias2[i] = v;
    }
}

// ---------------- LayerNorm (optional fused -3 cyclic shift) ----------------
__global__ void __launch_bounds__(256) ln_kernel(
    const float* __restrict__ in, const float* __restrict__ gam,
    const float* __restrict__ bet, __nv_bfloat16* __restrict__ out, int shift)
{
    int warp = (blockIdx.x * blockDim.x + threadIdx.x) >> 5;
    int lane = threadIdx.x & 31;
    if (warp >= TOKENS) return;
    int t = warp;
    size_t src;
    if (shift) {
        int b = t / TOK_IMG;
        int r = (t / HW) % HW;
        int c = t % HW;
        src = (size_t)(b * TOK_IMG + ((r + 3) % HW) * HW + ((c + 3) % HW)) * DIM;
    } else {
        src = (size_t)t * DIM;
    }
    float v[6];
    float s = 0.f, sq = 0.f;
#pragma unroll
    for (int k = 0; k < 6; k++) {
        v[k] = in[src + lane + 32*k];
        s += v[k]; sq += v[k]*v[k];
    }
#pragma unroll
    for (int o = 16; o > 0; o >>= 1) {
        s  += __shfl_xor_sync(0xffffffffu, s,  o);
        sq += __shfl_xor_sync(0xffffffffu, sq, o);
    }
    float mean = s * (1.f/DIM);
    float var  = sq * (1.f/DIM) - mean*mean;
    float rstd = rsqrtf(var + 1e-5f);
    size_t dst = (size_t)t * DIM;
#pragma unroll
    for (int k = 0; k < 6; k++) {
        int c = lane + 32*k;
        out[dst + c] = __float2bfloat16((v[k] - mean) * rstd * gam[c] + bet[c]);
    }
}

// ---------------- GEMM: 256x64 tile, K-tile 64, 2-stage cp.async ----------------
enum { EPI_QKV = 0, EPI_PROJ = 1, EPI_MLP1 = 2, EPI_MLP2 = 3 };

#define A_STRIDE 72
#define STAGE_A  (256*A_STRIDE)
#define STAGE_B  (64*A_STRIDE)
#define STAGE_EL (STAGE_A + STAGE_B)
#define STAGE_BY (STAGE_EL*2)
#define GEMM_SMEM (2*STAGE_BY)

template<int EPI>
__global__ void __launch_bounds__(256) gemm_bf16(
    const __nv_bfloat16* __restrict__ A, const __nv_bfloat16* __restrict__ B,
    int K, int N,
    const float* __restrict__ bias, const float* __restrict__ resid,
    float* __restrict__ outF, __nv_bfloat16* __restrict__ outH)
{
    extern __shared__ __align__(16) unsigned char smem[];
    int tid  = threadIdx.x;
    int warp = tid >> 5;
    int wm   = warp >> 1;
    int wn   = warp & 1;
    int row0 = blockIdx.y * 256;
    int col0 = blockIdx.x * 64;

    wmma::fragment<wmma::accumulator,16,16,16,float> acc[4][2];
#pragma unroll
    for (int i = 0; i < 4; i++)
#pragma unroll
        for (int j = 0; j < 2; j++) wmma::fill_fragment(acc[i][j], 0.f);

    auto loadStage = [&](int kb, int s) {
        __nv_bfloat16* As = (__nv_bfloat16*)(smem + (size_t)s * STAGE_BY);
        __nv_bfloat16* Bs = As + STAGE_A;
#pragma unroll
        for (int l = 0; l < 8; l++) {
            int v = tid + l*256;
            int r = v >> 3, c = (v & 7) * 8;
            cp16(&As[r*A_STRIDE + c], A + (size_t)(row0 + r)*K + kb + c);
        }
#pragma unroll
        for (int l = 0; l < 2; l++) {
            int v = tid + l*256;
            int r = v >> 3, c = (v & 7) * 8;
            cp16(&Bs[r*A_STRIDE + c], B + (size_t)(kb + r)*N + col0 + c);
        }
        cp_commit();
    };

    int nk = K >> 6;
    loadStage(0, 0);
    for (int kb = 0; kb < nk; kb++) {
        if (kb + 1 < nk) { loadStage((kb + 1) << 6, (kb + 1) & 1); cp_wait<1>(); }
        else             { cp_wait<0>(); }
        __syncthreads();
        __nv_bfloat16* As = (__nv_bfloat16*)(smem + (size_t)(kb & 1) * STAGE_BY);
        __nv_bfloat16* Bs = As + STAGE_A;
#pragma unroll
        for (int kk = 0; kk < 64; kk += 16) {
            wmma::fragment<wmma::matrix_a,16,16,16,__nv_bfloat16,wmma::row_major> af[4];
            wmma::fragment<wmma::matrix_b,16,16,16,__nv_bfloat16,wmma::row_major> bfr[2];
#pragma unroll
            for (int i = 0; i < 4; i++)
                wmma::load_matrix_sync(af[i], &As[(wm*64 + i*16)*A_STRIDE + kk], A_STRIDE);
#pragma unroll
            for (int j = 0; j < 2; j++)
                wmma::load_matrix_sync(bfr[j], &Bs[kk*A_STRIDE + wn*32 + j*16], A_STRIDE);
#pragma unroll
            for (int i = 0; i < 4; i++)
#pragma unroll
                for (int j = 0; j < 2; j++)
                    wmma::mma_sync(acc[i][j], af[i], bfr[j], acc[i][j]);
        }
        __syncthreads();
    }

    float* Cs = (float*)smem;
#pragma unroll
    for (int i = 0; i < 4; i++)
#pragma unroll
        for (int j = 0; j < 2; j++)
            wmma::store_matrix_sync(&Cs[(wm*64 + i*16)*68 + wn*32 + j*16], acc[i][j], 68, wmma::mem_row_major);
    __syncthreads();

#pragma unroll
    for (int l = 0; l < 16; l++) {
        int e  = tid + l*256;
        int r  = e >> 4;
        int cg = (e & 15) * 4;
        float4 v = *(float4*)&Cs[r*68 + cg];
        int grow = row0 + r, gcol = col0 + cg;
        if (EPI == EPI_QKV) {
            __nv_bfloat162 h0 = __floats2bfloat162_rn(v.x, v.y);
            __nv_bfloat162 h1 = __floats2bfloat162_rn(v.z, v.w);
            uint2 pk = make_uint2(*(unsigned*)&h0, *(unsigned*)&h1);
            *(uint2*)&outH[(size_t)grow*N + gcol] = pk;
        } else if (EPI == EPI_PROJ) {
            float4 bb = *(const float4*)(bias + gcol);
            int b  = grow / TOK_IMG;
            int rr = (grow / HW) % HW;
            int cc = grow % HW;
            int drow = b * TOK_IMG + ((rr + 3) % HW) * HW + ((cc + 3) % HW);
            float4 rs = *(const float4*)(resid + (size_t)drow*DIM + gcol);
            v.x += bb.x + rs.x; v.y += bb.y + rs.y; v.z += bb.z + rs.z; v.w += bb.w + rs.w;
            *(float4*)(outF + (size_t)drow*DIM + gcol) = v;
        } else if (EPI == EPI_MLP1) {
            float4 bb = *(const float4*)(bias + gcol);
            v.x += bb.x; v.y += bb.y; v.z += bb.z; v.w += bb.w;
            v.x = 0.5f*v.x*(1.f + erff(v.x*0.7071067811865476f));
            v.y = 0.5f*v.y*(1.f + erff(v.y*0.7071067811865476f));
            v.z = 0.5f*v.z*(1.f + erff(v.z*0.7071067811865476f));
            v.w = 0.5f*v.w*(1.f + erff(v.w*0.7071067811865476f));
            __nv_bfloat162 h0 = __floats2bfloat162_rn(v.x, v.y);
            __nv_bfloat162 h1 = __floats2bfloat162_rn(v.z, v.w);
            uint2 pk = make_uint2(*(unsigned*)&h0, *(unsigned*)&h1);
            *(uint2*)&outH[(size_t)grow*N + gcol] = pk;
        } else {
            float4 bb = *(const float4*)(bias + gcol);
            float4 rs = *(const float4*)(resid + (size_t)grow*DIM + gcol);
            v.x += bb.x + rs.x; v.y += bb.y + rs.y; v.z += bb.z + rs.z; v.w += bb.w + rs.w;
            *(float4*)(outF + (size_t)grow*DIM + gcol) = v;
        }
    }
}

// ---------------- window attention v3: register-resident mma.sync ----------------
// block = (head, window, batch), 128 threads / 4 warps; warp owns a 16-row strip.
// Scores/probs never touch smem. One __syncthreads total.
__global__ void __launch_bounds__(128) attn_kernel(
    const __nv_bfloat16* __restrict__ qkv, const float* __restrict__ bias2,
    __nv_bfloat16* __restrict__ outA)
{
    __shared__ __align__(16) __nv_bfloat16 sQ[64*40];
    __shared__ __align__(16) __nv_bfloat16 sK[64*40];
    __shared__ __align__(16) __nv_bfloat16 sV[64*40];

    int tid = threadIdx.x, w = tid >> 5, lane = tid & 31;
    int h = blockIdx.x, win = blockIdx.y, b = blockIdx.z;
    int wi = win >> 4, wj = win & 15;
    bool mul = (wi == NWIN-1), mlr = (wj == NWIN-1);
    int tokbase = (b*HW + wi*WS)*HW + wj*WS;

    // zero V pad rows 49..63 (cols 0..31) — P is 0 there but 0*garbage=NaN must be avoided
    uint4 z4 = make_uint4(0,0,0,0);
    for (int e = tid; e < 60; e += 128) {
        int rr = 49 + (e >> 2), ch = e & 3;
        *(uint4*)&sV[rr*40 + ch*8] = z4;
    }
    // load 49 rows of Q,K,V
    for (int e = tid; e < 196; e += 128) {
        int i = e >> 2, ch = e & 3;
        int t = tokbase + (i/WS)*HW + (i%WS);
        const __nv_bfloat16* p = qkv + (size_t)t*576 + h*HD + ch*8;
        *(uint4*)&sQ[i*40 + ch*8] = *(const uint4*)(p);
        *(uint4*)&sK[i*40 + ch*8] = *(const uint4*)(p + 192);
        *(uint4*)&sV[i*40 + ch*8] = *(const uint4*)(p + 384);
    }
    __syncthreads();

    int g = lane >> 3, r = lane & 7;

    // Q a-frags: 16 rows (w*16..) x 32 k
    unsigned qa[2][4];
#pragma unroll
    for (int kt = 0; kt < 2; kt++)
        ldsm4(qa[kt], &sQ[(w*16 + (g & 1)*8 + r)*40 + kt*16 + (g >> 1)*8]);

    // S = Q@K^T : 8 n-tiles of 8 cols
    float acc[8][4];
#pragma unroll
    for (int t = 0; t < 8; t++) { acc[t][0]=acc[t][1]=acc[t][2]=acc[t][3]=0.f; }
#pragma unroll
    for (int nt = 0; nt < 4; nt++) {
#pragma unroll
        for (int kt = 0; kt < 2; kt++) {
            unsigned bk[4];
            ldsm4(bk, &sK[(nt*16 + (g >> 1)*8 + r)*40 + kt*16 + (g & 1)*8]);
            mma16816(acc[nt*2],     qa[kt], bk);
            mma16816(acc[nt*2 + 1], qa[kt], bk + 2);
        }
    }

    // softmax in registers: thread holds rows (lane/4, lane/4+8) x 16 cols
    const float SC = 0.17677669529663689f;
    int q2 = (lane & 3)*2;
    bool jb[16], j7[16], jp[16];
#pragma unroll
    for (int e = 0; e < 16; e++) {
        int j = (e >> 1)*8 + q2 + (e & 1);
        jb[e] = (j >= 28); j7[e] = ((j % 7) >= 4); jp[e] = (j >= WS2);
    }
#pragma unroll
    for (int sel = 0; sel < 2; sel++) {
        int i = w*16 + (lane >> 2) + sel*8;
        bool ib = (i >= 28), i7 = ((i % 7) >= 4);
        float v[16];
        float mx = -1e30f;
#pragma unroll
        for (int t = 0; t < 8; t++) {
            float2 bb = *(const float2*)&bias2[i*64 + t*8 + q2];
            float v0 = fmaf(acc[t][sel*2],     SC, bb.x);
            float v1 = fmaf(acc[t][sel*2 + 1], SC, bb.y);
            if (mul && (ib != jb[2*t]))     v0 -= 1e9f;
            if (mlr && (i7 != j7[2*t]))     v0 -= 1e9f;
            if (mul && (ib != jb[2*t + 1])) v1 -= 1e9f;
            if (mlr && (i7 != j7[2*t + 1])) v1 -= 1e9f;
            if (jp[2*t])     v0 = -1e9f;   // select, not add: garbage-K safe
            if (jp[2*t + 1]) v1 = -1e9f;
            v[2*t] = v0; v[2*t + 1] = v1;
            mx = fmaxf(mx, fmaxf(v0, v1));
        }
        mx = fmaxf(mx, __shfl_xor_sync(0xffffffffu, mx, 1));
        mx = fmaxf(mx, __shfl_xor_sync(0xffffffffu, mx, 2));
        float sum = 0.f;
#pragma unroll
        for (int e = 0; e < 16; e++) { float ev = __expf(v[e] - mx); v[e] = ev; sum += ev; }
        sum += __shfl_xor_sync(0xffffffffu, sum, 1);
        sum += __shfl_xor_sync(0xffffffffu, sum, 2);
        float inv = 1.f / sum;
#pragma unroll
        for (int t = 0; t < 8; t++) {
            acc[t][sel*2]     = v[2*t] * inv;
            acc[t][sel*2 + 1] = v[2*t + 1] * inv;
        }
    }

    // O = P@V : P a-frags are a pure register repack of score accumulators
    float o[4][4];
#pragma unroll
    for (int t = 0; t < 4; t++) { o[t][0]=o[t][1]=o[t][2]=o[t][3]=0.f; }
#pragma unroll
    for (int kt = 0; kt < 4; kt++) {
        unsigned pa[4];
        __nv_bfloat162 t0 = __floats2bfloat162_rn(acc[2*kt][0],     acc[2*kt][1]);
        __nv_bfloat162 t1 = __floats2bfloat162_rn(acc[2*kt][2],     acc[2*kt][3]);
        __nv_bfloat162 t2 = __floats2bfloat162_rn(acc[2*kt + 1][0], acc[2*kt + 1][1]);
        __nv_bfloat162 t3 = __floats2bfloat162_rn(acc[2*kt + 1][2], acc[2*kt + 1][3]);
        pa[0] = *(unsigned*)&t0; pa[1] = *(unsigned*)&t1;
        pa[2] = *(unsigned*)&t2; pa[3] = *(unsigned*)&t3;
        unsigned bv[4];
        ldsm4t(bv, &sV[(kt*16 + (g & 1)*8 + r)*40 + (g >> 1)*8]);
        mma16816(o[0], pa, bv);
        mma16816(o[1], pa, bv + 2);
        ldsm4t(bv, &sV[(kt*16 + (g & 1)*8 + r)*40 + 16 + (g >> 1)*8]);
        mma16816(o[2], pa, bv);
        mma16816(o[3], pa, bv + 2);
    }

    // write outputs straight from accumulators
#pragma unroll
    for (int sel = 0; sel < 2; sel++) {
        int i = w*16 + (lane >> 2) + sel*8;
        if (i < WS2) {
            int tok = tokbase + (i/WS)*HW + (i%WS);
            __nv_bfloat16* po = outA + (size_t)tok*INNER + h*HD + q2;
#pragma unroll
            for (int dt = 0; dt < 4; dt++) {
                __nv_bfloat162 pr = __floats2bfloat162_rn(o[dt][sel*2], o[dt][sel*2 + 1]);
                *(__nv_bfloat162*)(po + dt*8) = pr;
            }
        }
    }
}

// ---------------- launch ----------------
extern "C" void kernel_launch(void* const* d_in, const int* in_sizes, int n_in,
                              void* d_out, int out_size)
{
    const float* x      = (const float*)d_in[0];
    const float* w_qkv  = (const float*)d_in[1];
    const float* w_out  = (const float*)d_in[2];
    const float* b_out  = (const float*)d_in[3];
    const float* pos    = (const float*)d_in[4];
    const float* ln1_g  = (const float*)d_in[5];
    const float* ln1_b  = (const float*)d_in[6];
    const float* ln2_g  = (const float*)d_in[7];
    const float* ln2_b  = (const float*)d_in[8];
    const float* w1     = (const float*)d_in[9];
    const float* b1     = (const float*)d_in[10];
    const float* w2     = (const float*)d_in[11];
    const float* b2     = (const float*)d_in[12];
    float* out = (float*)d_out;

    void *p_y, *p_qkv, *p_attn, *p_x2, *p_h, *p_mlp;
    void *p_wqkv, *p_wout, *p_w1, *p_w2, *p_bias;
    cudaGetSymbolAddress(&p_y,    g_y);
    cudaGetSymbolAddress(&p_qkv,  g_qkv);
    cudaGetSymbolAddress(&p_attn, g_attn);
    cudaGetSymbolAddress(&p_x2,   g_x2);
    cudaGetSymbolAddress(&p_h,    g_h);
    cudaGetSymbolAddress(&p_mlp,  g_mlp);
    cudaGetSymbolAddress(&p_wqkv, g_wqkv);
    cudaGetSymbolAddress(&p_wout, g_wout);
    cudaGetSymbolAddress(&p_w1,   g_w1);
    cudaGetSymbolAddress(&p_w2,   g_w2);
    cudaGetSymbolAddress(&p_bias, g_bias2);

    static bool attr_done = false;
    if (!attr_done) {
        cudaFuncSetAttribute(gemm_bf16<EPI_QKV>,  cudaFuncAttributeMaxDynamicSharedMemorySize, GEMM_SMEM);
        cudaFuncSetAttribute(gemm_bf16<EPI_PROJ>, cudaFuncAttributeMaxDynamicSharedMemorySize, GEMM_SMEM);
        cudaFuncSetAttribute(gemm_bf16<EPI_MLP1>, cudaFuncAttributeMaxDynamicSharedMemorySize, GEMM_SMEM);
        cudaFuncSetAttribute(gemm_bf16<EPI_MLP2>, cudaFuncAttributeMaxDynamicSharedMemorySize, GEMM_SMEM);
        attr_done = true;
    }

    convert_kernel<<<(SZ_ALL + 64*64 + 255)/256, 256>>>(
        w_qkv, w_out, w1, w2, pos,
        (__nv_bfloat16*)p_wqkv, (__nv_bfloat16*)p_wout,
        (__nv_bfloat16*)p_w1, (__nv_bfloat16*)p_w2, (float*)p_bias);

    ln_kernel<<<TOKENS/8, 256>>>(x, ln1_g, ln1_b, (__nv_bfloat16*)p_y, 1);

    gemm_bf16<EPI_QKV><<<dim3(576/64, TOKENS/256), 256, GEMM_SMEM>>>(
        (const __nv_bfloat16*)p_y, (const __nv_bfloat16*)p_wqkv, DIM, 576,
        nullptr, nullptr, nullptr, (__nv_bfloat16*)p_qkv);

    attn_kernel<<<dim3(HEADS, NWIN*NWIN, BATCH), 128>>>(
        (const __nv_bfloat16*)p_qkv, (const float*)p_bias, (__nv_bfloat16*)p_attn);

    gemm_bf16<EPI_PROJ><<<dim3(DIM/64, TOKENS/256), 256, GEMM_SMEM>>>(
        (const __nv_bfloat16*)p_attn, (const __nv_bfloat16*)p_wout, INNER, DIM,
        b_out, x, (float*)p_x2, nullptr);

    ln_kernel<<<TOKENS/8, 256>>>((const float*)p_x2, ln2_g, ln2_b, (__nv_bfloat16*)p_h, 0);

    gemm_bf16<EPI_MLP1><<<dim3(MLPD/64, TOKENS/256), 256, GEMM_SMEM>>>(
        (const __nv_bfloat16*)p_h, (const __nv_bfloat16*)p_w1, DIM, MLPD,
        b1, nullptr, nullptr, (__nv_bfloat16*)p_mlp);

    gemm_bf16<EPI_MLP2><<<dim3(DIM/64, TOKENS/256), 256, GEMM_SMEM>>>(
        (const __nv_bfloat16*)p_mlp, (const __nv_bfloat16*)p_w2, MLPD, DIM,
        b2, (const float*)p_x2, out, nullptr);
}

// round 6
// speedup vs baseline: 2.0822x; 1.1287x over previous
#include <cuda_runtime.h>
#include <cuda_bf16.h>

// ---------------- problem constants ----------------
#define BATCH   8
#define HW      112
#define DIM     192
#define HEADS   6
#define HD      32
#define INNER   192
#define MLPD    768
#define WS      7
#define WS2     49
#define NWIN    16
#define TOKENS  (BATCH*HW*HW)        // 100352
#define TOK_IMG (HW*HW)              // 12544

// ---------------- scratch ----------------
__device__ __nv_bfloat16 g_y   [(size_t)TOKENS*DIM];
__device__ __nv_bfloat16 g_qkv [(size_t)TOKENS*576];
__device__ __nv_bfloat16 g_attn[(size_t)TOKENS*INNER];
__device__ float         g_x2  [(size_t)TOKENS*DIM];
__device__ __nv_bfloat16 g_h   [(size_t)TOKENS*DIM];
__device__ __nv_bfloat16 g_mlp [(size_t)TOKENS*MLPD];
__device__ __nv_bfloat16 g_wqkvT[576*DIM];     // [N][K] transposed
__device__ __nv_bfloat16 g_woutT[DIM*INNER];
__device__ __nv_bfloat16 g_w1T  [MLPD*DIM];
__device__ __nv_bfloat16 g_w2T  [DIM*MLPD];
__device__ float         g_bias2[64*64];

// ---------------- helpers ----------------
__device__ __forceinline__ void cp16(void* s, const void* g) {
    unsigned sa = (unsigned)__cvta_generic_to_shared(s);
    asm volatile("cp.async.cg.shared.global [%0], [%1], 16;\n" :: "r"(sa), "l"(g));
}
__device__ __forceinline__ void cp_commit() { asm volatile("cp.async.commit_group;\n"); }
template<int N> __device__ __forceinline__ void cp_wait() {
    asm volatile("cp.async.wait_group %0;\n" :: "n"(N));
}
__device__ __forceinline__ void ldsm4(unsigned* r, const void* p) {
    unsigned a = (unsigned)__cvta_generic_to_shared(p);
    asm volatile("ldmatrix.sync.aligned.m8n8.x4.shared.b16 {%0,%1,%2,%3}, [%4];\n"
        : "=r"(r[0]),"=r"(r[1]),"=r"(r[2]),"=r"(r[3]) : "r"(a));
}
__device__ __forceinline__ void ldsm4t(unsigned* r, const void* p) {
    unsigned a = (unsigned)__cvta_generic_to_shared(p);
    asm volatile("ldmatrix.sync.aligned.m8n8.x4.trans.shared.b16 {%0,%1,%2,%3}, [%4];\n"
        : "=r"(r[0]),"=r"(r[1]),"=r"(r[2]),"=r"(r[3]) : "r"(a));
}
__device__ __forceinline__ void mma16816(float* d, const unsigned* a, const unsigned* b) {
    asm volatile("mma.sync.aligned.m16n8k16.row.col.f32.bf16.bf16.f32 "
        "{%0,%1,%2,%3}, {%4,%5,%6,%7}, {%8,%9}, {%0,%1,%2,%3};\n"
        : "+f"(d[0]),"+f"(d[1]),"+f"(d[2]),"+f"(d[3])
        : "r"(a[0]),"r"(a[1]),"r"(a[2]),"r"(a[3]), "r"(b[0]),"r"(b[1]));
}

// ---------------- weight transpose convert + padded rel-bias ----------------
#define SZ_QKV (576*DIM)
#define SZ_OUT (DIM*INNER)
#define SZ_W1  (MLPD*DIM)
#define SZ_W2  (DIM*MLPD)
#define SZ_ALL (SZ_QKV+SZ_OUT+SZ_W1+SZ_W2)
__global__ void convert_kernel(
    const float* __restrict__ wqkv, const float* __restrict__ wout,
    const float* __restrict__ w1, const float* __restrict__ w2,
    const float* __restrict__ pos,
    __nv_bfloat16* __restrict__ o_qkvT, __nv_bfloat16* __restrict__ o_outT,
    __nv_bfloat16* __restrict__ o_w1T, __nv_bfloat16* __restrict__ o_w2T,
    float* __restrict__ bias2)
{
    int i = blockIdx.x * blockDim.x + threadIdx.x;
    if (i < SZ_QKV) { int n=i/192,k=i%192; o_qkvT[i]=__float2bfloat16(wqkv[k*576+n]); return; }
    i -= SZ_QKV;
    if (i < SZ_OUT) { int n=i/192,k=i%192; o_outT[i]=__float2bfloat16(wout[k*192+n]); return; }
    i -= SZ_OUT;
    if (i < SZ_W1)  { int n=i/192,k=i%192; o_w1T[i]=__float2bfloat16(w1[k*768+n]); return; }
    i -= SZ_W1;
    if (i < SZ_W2)  { int n=i/768,k=i%768; o_w2T[i]=__float2bfloat16(w2[k*192+n]); return; }
    i -= SZ_W2;
    if (i < 64*64) {
        int r = i >> 6, c = i & 63;
        float v = 0.f;
        if (r < WS2 && c < WS2) {
            int ri = r / WS, ci = r % WS, rj = c / WS, cj = c % WS;
            v = pos[(ri - rj + WS - 1) * (2*WS - 1) + (ci - cj + WS - 1)];
        }
        bias2[i] = v;
    }
}

// ---------------- LayerNorm (optional fused -3 cyclic shift) ----------------
__global__ void __launch_bounds__(256) ln_kernel(
    const float* __restrict__ in, const float* __restrict__ gam,
    const float* __restrict__ bet, __nv_bfloat16* __restrict__ out, int shift)
{
    int warp = (blockIdx.x * blockDim.x + threadIdx.x) >> 5;
    int lane = threadIdx.x & 31;
    if (warp >= TOKENS) return;
    int t = warp;
    size_t src;
    if (shift) {
        int b = t / TOK_IMG;
        int r = (t / HW) % HW;
        int c = t % HW;
        src = (size_t)(b * TOK_IMG + ((r + 3) % HW) * HW + ((c + 3) % HW)) * DIM;
    } else {
        src = (size_t)t * DIM;
    }
    float v[6];
    float s = 0.f, sq = 0.f;
#pragma unroll
    for (int k = 0; k < 6; k++) {
        v[k] = in[src + lane + 32*k];
        s += v[k]; sq += v[k]*v[k];
    }
#pragma unroll
    for (int o = 16; o > 0; o >>= 1) {
        s  += __shfl_xor_sync(0xffffffffu, s,  o);
        sq += __shfl_xor_sync(0xffffffffu, sq, o);
    }
    float mean = s * (1.f/DIM);
    float rstd = rsqrtf(sq * (1.f/DIM) - mean*mean + 1e-5f);
    size_t dst = (size_t)t * DIM;
#pragma unroll
    for (int k = 0; k < 6; k++) {
        int c = lane + 32*k;
        out[dst + c] = __float2bfloat16((v[k] - mean) * rstd * gam[c] + bet[c]);
    }
}

// ---------------- raw mma GEMM: C = A[M,K] @ Bt[N,K]^T ----------------
// CTA tile 256x64, K-tile 64, 2-stage cp.async, warp tile 64x32.
// Direct register epilogue (no smem roundtrip).
enum { EPI_QKV = 0, EPI_PROJ = 1, EPI_MLP1 = 2, EPI_MLP2 = 3 };

#define GSTRIDE 72
#define STAGE_A  (256*GSTRIDE)
#define STAGE_B  (64*GSTRIDE)
#define STAGE_EL (STAGE_A + STAGE_B)
#define STAGE_BY (STAGE_EL*2)
#define GEMM_SMEM (2*STAGE_BY)          // 92160 bytes

template<int EPI>
__global__ void __launch_bounds__(256, 2) gemm_bf16(
    const __nv_bfloat16* __restrict__ A, const __nv_bfloat16* __restrict__ Bt,
    int K, int Nfull,
    const float* __restrict__ bias, const float* __restrict__ resid,
    float* __restrict__ outF, __nv_bfloat16* __restrict__ outH)
{
    extern __shared__ __align__(16) unsigned char smem[];
    const int tid  = threadIdx.x;
    const int warp = tid >> 5;
    const int lane = tid & 31;
    const int wm   = warp >> 1;       // 0..3 : 64-row strip
    const int wn   = warp & 1;        // 0..1 : 32-col strip
    const int row0 = blockIdx.y * 256;
    const int col0 = blockIdx.x * 64;
    const int g    = lane >> 3;
    const int r8   = lane & 7;

    float acc[4][4][4];               // [m16][n8][frag]
#pragma unroll
    for (int mt = 0; mt < 4; mt++)
#pragma unroll
        for (int nt = 0; nt < 4; nt++)
            acc[mt][nt][0]=acc[mt][nt][1]=acc[mt][nt][2]=acc[mt][nt][3]=0.f;

    auto loadStage = [&](int kb, int s) {
        __nv_bfloat16* As = (__nv_bfloat16*)(smem + (size_t)s * STAGE_BY);
        __nv_bfloat16* Bs = As + STAGE_A;
#pragma unroll
        for (int l = 0; l < 8; l++) {               // A: 2048 16B chunks
            int v = tid + l*256;
            int rr = v >> 3, c = (v & 7) * 8;
            cp16(&As[rr*GSTRIDE + c], A + (size_t)(row0 + rr)*K + kb + c);
        }
#pragma unroll
        for (int l = 0; l < 2; l++) {               // B: 512 chunks ([N][K] rows)
            int v = tid + l*256;
            int rn = v >> 3, c = (v & 7) * 8;
            cp16(&Bs[rn*GSTRIDE + c], Bt + (size_t)(col0 + rn)*K + kb + c);
        }
        cp_commit();
    };

    const int T = K >> 6;
    loadStage(0, 0);
    for (int t = 0; t < T; t++) {
        cp_wait<0>();
        __syncthreads();
        if (t + 1 < T) loadStage((t + 1) << 6, (t + 1) & 1);
        __nv_bfloat16* As = (__nv_bfloat16*)(smem + (size_t)(t & 1) * STAGE_BY);
        __nv_bfloat16* Bs = As + STAGE_A;
#pragma unroll
        for (int kk = 0; kk < 64; kk += 16) {
            unsigned af[4][4];
#pragma unroll
            for (int mt = 0; mt < 4; mt++)
                ldsm4(af[mt], &As[(wm*64 + mt*16 + (g & 1)*8 + r8)*GSTRIDE + kk + (g >> 1)*8]);
#pragma unroll
            for (int nt16 = 0; nt16 < 2; nt16++) {
                unsigned bf2[4];
                ldsm4(bf2, &Bs[(wn*32 + nt16*16 + (g >> 1)*8 + r8)*GSTRIDE + kk + (g & 1)*8]);
#pragma unroll
                for (int mt = 0; mt < 4; mt++) {
                    mma16816(acc[mt][nt16*2],     af[mt], bf2);
                    mma16816(acc[mt][nt16*2 + 1], af[mt], bf2 + 2);
                }
            }
        }
    }

    // ---------------- direct epilogue ----------------
    const int lr = lane >> 2;
    const int lc = (lane & 3) * 2;
    const int cbase = col0 + wn*32;

#pragma unroll
    for (int mt = 0; mt < 4; mt++) {
#pragma unroll
        for (int half = 0; half < 2; half++) {
            int gr = row0 + wm*64 + mt*16 + lr + half*8;
            if (EPI == EPI_QKV) {
                __nv_bfloat16* orow = outH + (size_t)gr*Nfull + cbase;
#pragma unroll
                for (int nt = 0; nt < 4; nt++) {
                    __nv_bfloat162 pr = __floats2bfloat162_rn(
                        acc[mt][nt][half*2], acc[mt][nt][half*2 + 1]);
                    *(__nv_bfloat162*)(orow + nt*8 + lc) = pr;
                }
            } else if (EPI == EPI_MLP1) {
                __nv_bfloat16* orow = outH + (size_t)gr*Nfull + cbase;
#pragma unroll
                for (int nt = 0; nt < 4; nt++) {
                    float v0 = acc[mt][nt][half*2]     + __ldg(bias + cbase + nt*8 + lc);
                    float v1 = acc[mt][nt][half*2 + 1] + __ldg(bias + cbase + nt*8 + lc + 1);
                    v0 = 0.5f*v0*(1.f + erff(v0*0.7071067811865476f));
                    v1 = 0.5f*v1*(1.f + erff(v1*0.7071067811865476f));
                    *(__nv_bfloat162*)(orow + nt*8 + lc) = __floats2bfloat162_rn(v0, v1);
                }
            } else if (EPI == EPI_PROJ) {
                int bq = gr / TOK_IMG;
                int rr = (gr / HW) % HW;
                int cc = gr % HW;
                int drow = bq * TOK_IMG + ((rr + 3) % HW) * HW + ((cc + 3) % HW);
                float* orow = outF + (size_t)drow*DIM + cbase;
                const float* rrow = resid + (size_t)drow*DIM + cbase;
#pragma unroll
                for (int nt = 0; nt < 4; nt++) {
                    float2 rs = *(const float2*)(rrow + nt*8 + lc);
                    float2 ov;
                    ov.x = acc[mt][nt][half*2]     + __ldg(bias + cbase + nt*8 + lc)     + rs.x;
                    ov.y = acc[mt][nt][half*2 + 1] + __ldg(bias + cbase + nt*8 + lc + 1) + rs.y;
                    *(float2*)(orow + nt*8 + lc) = ov;
                }
            } else { // EPI_MLP2
                float* orow = outF + (size_t)gr*DIM + cbase;
                const float* rrow = resid + (size_t)gr*DIM + cbase;
#pragma unroll
                for (int nt = 0; nt < 4; nt++) {
                    float2 rs = *(const float2*)(rrow + nt*8 + lc);
                    float2 ov;
                    ov.x = acc[mt][nt][half*2]     + __ldg(bias + cbase + nt*8 + lc)     + rs.x;
                    ov.y = acc[mt][nt][half*2 + 1] + __ldg(bias + cbase + nt*8 + lc + 1) + rs.y;
                    *(float2*)(orow + nt*8 + lc) = ov;
                }
            }
        }
    }
}

// ---------------- window attention (register-resident mma.sync) ----------------
__global__ void __launch_bounds__(128) attn_kernel(
    const __nv_bfloat16* __restrict__ qkv, const float* __restrict__ bias2,
    __nv_bfloat16* __restrict__ outA)
{
    __shared__ __align__(16) __nv_bfloat16 sQ[64*40];
    __shared__ __align__(16) __nv_bfloat16 sK[64*40];
    __shared__ __align__(16) __nv_bfloat16 sV[64*40];

    int tid = threadIdx.x, w = tid >> 5, lane = tid & 31;
    int h = blockIdx.x, win = blockIdx.y, b = blockIdx.z;
    int wi = win >> 4, wj = win & 15;
    bool mul = (wi == NWIN-1), mlr = (wj == NWIN-1);
    int tokbase = (b*HW + wi*WS)*HW + wj*WS;

    uint4 z4 = make_uint4(0,0,0,0);
    for (int e = tid; e < 60; e += 128) {
        int rr = 49 + (e >> 2), ch = e & 3;
        *(uint4*)&sV[rr*40 + ch*8] = z4;
    }
    for (int e = tid; e < 196; e += 128) {
        int i = e >> 2, ch = e & 3;
        int t = tokbase + (i/WS)*HW + (i%WS);
        const __nv_bfloat16* p = qkv + (size_t)t*576 + h*HD + ch*8;
        *(uint4*)&sQ[i*40 + ch*8] = *(const uint4*)(p);
        *(uint4*)&sK[i*40 + ch*8] = *(const uint4*)(p + 192);
        *(uint4*)&sV[i*40 + ch*8] = *(const uint4*)(p + 384);
    }
    __syncthreads();

    int g = lane >> 3, r = lane & 7;

    unsigned qa[2][4];
#pragma unroll
    for (int kt = 0; kt < 2; kt++)
        ldsm4(qa[kt], &sQ[(w*16 + (g & 1)*8 + r)*40 + kt*16 + (g >> 1)*8]);

    float acc[8][4];
#pragma unroll
    for (int t = 0; t < 8; t++) { acc[t][0]=acc[t][1]=acc[t][2]=acc[t][3]=0.f; }
#pragma unroll
    for (int nt = 0; nt < 4; nt++) {
#pragma unroll
        for (int kt = 0; kt < 2; kt++) {
            unsigned bk[4];
            ldsm4(bk, &sK[(nt*16 + (g >> 1)*8 + r)*40 + kt*16 + (g & 1)*8]);
            mma16816(acc[nt*2],     qa[kt], bk);
            mma16816(acc[nt*2 + 1], qa[kt], bk + 2);
        }
    }

    const float SC = 0.17677669529663689f;
    int q2 = (lane & 3)*2;
    bool jb[16], j7[16], jp[16];
#pragma unroll
    for (int e = 0; e < 16; e++) {
        int j = (e >> 1)*8 + q2 + (e & 1);
        jb[e] = (j >= 28); j7[e] = ((j % 7) >= 4); jp[e] = (j >= WS2);
    }
#pragma unroll
    for (int sel = 0; sel < 2; sel++) {
        int i = w*16 + (lane >> 2) + sel*8;
        bool ib = (i >= 28), i7 = ((i % 7) >= 4);
        float v[16];
        float mx = -1e30f;
#pragma unroll
        for (int t = 0; t < 8; t++) {
            float2 bb = *(const float2*)&bias2[i*64 + t*8 + q2];
            float v0 = fmaf(acc[t][sel*2],     SC, bb.x);
            float v1 = fmaf(acc[t][sel*2 + 1], SC, bb.y);
            if (mul && (ib != jb[2*t]))     v0 -= 1e9f;
            if (mlr && (i7 != j7[2*t]))     v0 -= 1e9f;
            if (mul && (ib != jb[2*t + 1])) v1 -= 1e9f;
            if (mlr && (i7 != j7[2*t + 1])) v1 -= 1e9f;
            if (jp[2*t])     v0 = -1e9f;
            if (jp[2*t + 1]) v1 = -1e9f;
            v[2*t] = v0; v[2*t + 1] = v1;
            mx = fmaxf(mx, fmaxf(v0, v1));
        }
        mx = fmaxf(mx, __shfl_xor_sync(0xffffffffu, mx, 1));
        mx = fmaxf(mx, __shfl_xor_sync(0xffffffffu, mx, 2));
        float sum = 0.f;
#pragma unroll
        for (int e = 0; e < 16; e++) { float ev = __expf(v[e] - mx); v[e] = ev; sum += ev; }
        sum += __shfl_xor_sync(0xffffffffu, sum, 1);
        sum += __shfl_xor_sync(0xffffffffu, sum, 2);
        float inv = 1.f / sum;
#pragma unroll
        for (int t = 0; t < 8; t++) {
            acc[t][sel*2]     = v[2*t] * inv;
            acc[t][sel*2 + 1] = v[2*t + 1] * inv;
        }
    }

    float o[4][4];
#pragma unroll
    for (int t = 0; t < 4; t++) { o[t][0]=o[t][1]=o[t][2]=o[t][3]=0.f; }
#pragma unroll
    for (int kt = 0; kt < 4; kt++) {
        unsigned pa[4];
        __nv_bfloat162 t0 = __floats2bfloat162_rn(acc[2*kt][0],     acc[2*kt][1]);
        __nv_bfloat162 t1 = __floats2bfloat162_rn(acc[2*kt][2],     acc[2*kt][3]);
        __nv_bfloat162 t2 = __floats2bfloat162_rn(acc[2*kt + 1][0], acc[2*kt + 1][1]);
        __nv_bfloat162 t3 = __floats2bfloat162_rn(acc[2*kt + 1][2], acc[2*kt + 1][3]);
        pa[0] = *(unsigned*)&t0; pa[1] = *(unsigned*)&t1;
        pa[2] = *(unsigned*)&t2; pa[3] = *(unsigned*)&t3;
        unsigned bv[4];
        ldsm4t(bv, &sV[(kt*16 + (g & 1)*8 + r)*40 + (g >> 1)*8]);
        mma16816(o[0], pa, bv);
        mma16816(o[1], pa, bv + 2);
        ldsm4t(bv, &sV[(kt*16 + (g & 1)*8 + r)*40 + 16 + (g >> 1)*8]);
        mma16816(o[2], pa, bv);
        mma16816(o[3], pa, bv + 2);
    }

#pragma unroll
    for (int sel = 0; sel < 2; sel++) {
        int i = w*16 + (lane >> 2) + sel*8;
        if (i < WS2) {
            int tok = tokbase + (i/WS)*HW + (i%WS);
            __nv_bfloat16* po = outA + (size_t)tok*INNER + h*HD + q2;
#pragma unroll
            for (int dt = 0; dt < 4; dt++) {
                __nv_bfloat162 pr = __floats2bfloat162_rn(o[dt][sel*2], o[dt][sel*2 + 1]);
                *(__nv_bfloat162*)(po + dt*8) = pr;
            }
        }
    }
}

// ---------------- launch ----------------
extern "C" void kernel_launch(void* const* d_in, const int* in_sizes, int n_in,
                              void* d_out, int out_size)
{
    const float* x      = (const float*)d_in[0];
    const float* w_qkv  = (const float*)d_in[1];
    const float* w_out  = (const float*)d_in[2];
    const float* b_out  = (const float*)d_in[3];
    const float* pos    = (const float*)d_in[4];
    const float* ln1_g  = (const float*)d_in[5];
    const float* ln1_b  = (const float*)d_in[6];
    const float* ln2_g  = (const float*)d_in[7];
    const float* ln2_b  = (const float*)d_in[8];
    const float* w1     = (const float*)d_in[9];
    const float* b1     = (const float*)d_in[10];
    const float* w2     = (const float*)d_in[11];
    const float* b2     = (const float*)d_in[12];
    float* out = (float*)d_out;

    void *p_y, *p_qkv, *p_attn, *p_x2, *p_h, *p_mlp;
    void *p_wqkvT, *p_woutT, *p_w1T, *p_w2T, *p_bias;
    cudaGetSymbolAddress(&p_y,    g_y);
    cudaGetSymbolAddress(&p_qkv,  g_qkv);
    cudaGetSymbolAddress(&p_attn, g_attn);
    cudaGetSymbolAddress(&p_x2,   g_x2);
    cudaGetSymbolAddress(&p_h,    g_h);
    cudaGetSymbolAddress(&p_mlp,  g_mlp);
    cudaGetSymbolAddress(&p_wqkvT, g_wqkvT);
    cudaGetSymbolAddress(&p_woutT, g_woutT);
    cudaGetSymbolAddress(&p_w1T,   g_w1T);
    cudaGetSymbolAddress(&p_w2T,   g_w2T);
    cudaGetSymbolAddress(&p_bias,  g_bias2);

    static bool attr_done = false;
    if (!attr_done) {
        cudaFuncSetAttribute(gemm_bf16<EPI_QKV>,  cudaFuncAttributeMaxDynamicSharedMemorySize, GEMM_SMEM);
        cudaFuncSetAttribute(gemm_bf16<EPI_PROJ>, cudaFuncAttributeMaxDynamicSharedMemorySize, GEMM_SMEM);
        cudaFuncSetAttribute(gemm_bf16<EPI_MLP1>, cudaFuncAttributeMaxDynamicSharedMemorySize, GEMM_SMEM);
        cudaFuncSetAttribute(gemm_bf16<EPI_MLP2>, cudaFuncAttributeMaxDynamicSharedMemorySize, GEMM_SMEM);
        attr_done = true;
    }

    convert_kernel<<<(SZ_ALL + 64*64 + 255)/256, 256>>>(
        w_qkv, w_out, w1, w2, pos,
        (__nv_bfloat16*)p_wqkvT, (__nv_bfloat16*)p_woutT,
        (__nv_bfloat16*)p_w1T, (__nv_bfloat16*)p_w2T, (float*)p_bias);

    ln_kernel<<<TOKENS/8, 256>>>(x, ln1_g, ln1_b, (__nv_bfloat16*)p_y, 1);

    // QKV: [100352,192] x [192,576]
    gemm_bf16<EPI_QKV><<<dim3(576/64, TOKENS/256), 256, GEMM_SMEM>>>(
        (const __nv_bfloat16*)p_y, (const __nv_bfloat16*)p_wqkvT, DIM, 576,
        nullptr, nullptr, nullptr, (__nv_bfloat16*)p_qkv);

    attn_kernel<<<dim3(HEADS, NWIN*NWIN, BATCH), 128>>>(
        (const __nv_bfloat16*)p_qkv, (const float*)p_bias, (__nv_bfloat16*)p_attn);

    // PROJ + back-shift + residual -> x2
    gemm_bf16<EPI_PROJ><<<dim3(DIM/64, TOKENS/256), 256, GEMM_SMEM>>>(
        (const __nv_bfloat16*)p_attn, (const __nv_bfloat16*)p_woutT, INNER, DIM,
        b_out, x, (float*)p_x2, nullptr);

    ln_kernel<<<TOKENS/8, 256>>>((const float*)p_x2, ln2_g, ln2_b, (__nv_bfloat16*)p_h, 0);

    // MLP1 + exact GELU
    gemm_bf16<EPI_MLP1><<<dim3(MLPD/64, TOKENS/256), 256, GEMM_SMEM>>>(
        (const __nv_bfloat16*)p_h, (const __nv_bfloat16*)p_w1T, DIM, MLPD,
        b1, nullptr, nullptr, (__nv_bfloat16*)p_mlp);

    // MLP2 + residual -> out
    gemm_bf16<EPI_MLP2><<<dim3(DIM/64, TOKENS/256), 256, GEMM_SMEM>>>(
        (const __nv_bfloat16*)p_mlp, (const __nv_bfloat16*)p_w2T, MLPD, DIM,
        b2, (const float*)p_x2, out, nullptr);
}